// round 6
// baseline (speedup 1.0000x reference)
#include <cuda_runtime.h>
#include <cstdint>

#define E_DIM 4096
#define N_DIM 8192
#define FIN   256
#define HEADS 8
#define DOUT  64
#define HD    512
#define BATCH 2
#define LRELU_ALPHA 0.2f
#define NSLICE 16

// ---------------- scratch ----------------
__device__ __align__(16) float g_xr[BATCH * N_DIM * FIN];    // k-perm16 cols
__device__ __align__(16) float g_WrT[HD * FIN];              // (hd, fin) k-perm16
__device__ __align__(16) float g_Hr[N_DIM * E_DIM];          // e-perm16 cols
__device__ __align__(16) float g_HT[E_DIM * N_DIM];          // n-perm16 cols
__device__ __align__(16) float g_Wh[BATCH * N_DIM * HD];     // natural (rounded)
__device__ __align__(16) float g_WhT[BATCH * HD * N_DIM];    // n-perm16 cols
__device__ __align__(16) float g_m2T[BATCH * HD * E_DIM];    // e-perm16 cols (rounded, ae-scaled)
__device__ float g_av[BATCH * N_DIM * HEADS];
__device__ float g_part[NSLICE * BATCH * E_DIM * HEADS];
__device__ float g_aeT[BATCH * HEADS * E_DIM];

__device__ __forceinline__ uint32_t f2tf32(float f) {
    uint32_t r; asm("cvt.rna.tf32.f32 %0, %1;" : "=r"(r) : "f"(f)); return r;
}
__device__ __forceinline__ float rnd(float f) { return __uint_as_float(f2tf32(f)); }
__device__ __forceinline__ uint32_t smem_u32(const void* p) {
    uint32_t a;
    asm("{ .reg .u64 t; cvta.to.shared.u64 t, %1; cvt.u32.u64 %0, t; }" : "=r"(a) : "l"(p));
    return a;
}
__device__ __forceinline__ void lds128(uint32_t a, uint32_t& x, uint32_t& y,
                                       uint32_t& z, uint32_t& w) {
    asm volatile("ld.shared.v4.b32 {%0,%1,%2,%3}, [%4];"
        : "=r"(x), "=r"(y), "=r"(z), "=r"(w) : "r"(a));
}
__device__ __forceinline__ void cpa16(uint32_t dst, const void* src) {
    asm volatile("cp.async.cg.shared.global [%0], [%1], 16;" :: "r"(dst), "l"(src));
}
// 16-wide K permutation: k -> (k&3)*4 + (k>>2)
__device__ __host__ __forceinline__ int perm16(int k) { return ((k & 3) << 2) | ((k >> 2) & 3); }
__device__ __forceinline__ int permc(int c) { return (c & ~15) | perm16(c & 15); }

#define MMA_TF32(c, a0, a1, a2, a3, b0, b1) \
    asm volatile("mma.sync.aligned.m16n8k8.row.col.f32.tf32.tf32.f32 " \
        "{%0,%1,%2,%3}, {%4,%5,%6,%7}, {%8,%9}, {%0,%1,%2,%3};" \
        : "+f"((c)[0]), "+f"((c)[1]), "+f"((c)[2]), "+f"((c)[3]) \
        : "r"(a0), "r"(a1), "r"(a2), "r"(a3), "r"(b0), "r"(b1))

#define STG_BYTES 32768               // A 16KB + B 16KB (128 rows x 128B each)
#define STAGES 3
#define SMEM_SZ (STAGES * STG_BYTES)  // 96 KB

// ---------------- tf32 mma GEMM: CTA 128x128, 4 warps (64x64 each), K-step 32 ----------------
// A: (M x K) rows m, k-perm16 cols.  B: (N x K) rows n, k-perm16 cols.  C: (M x N) row-major.
// EPI 0: round   EPI 1: scale by aeT[bz,head(row),e(col)] + round + perm16-col store   EPI 2: plain
template<int EPI>
__global__ void __launch_bounds__(128, 2) tgemm(
    const float* __restrict__ A, const float* __restrict__ B, float* __restrict__ C,
    int K, int lda, int ldb, int ldc,
    long strideA, long strideB, long strideC, const float* __restrict__ aeT)
{
    extern __shared__ char smem[];
    const uint32_t sb = smem_u32(smem);
    const int tid = threadIdx.x, lane = tid & 31, wid = tid >> 5;
    const int wm = wid >> 1, wn = wid & 1;
    const int m0 = blockIdx.y * 128, n0 = blockIdx.x * 128, bz = blockIdx.z;

    const float* Ag = A + (long)bz * strideA + (long)m0 * lda;
    const float* Bg = B + (long)bz * strideB + (long)n0 * ldb;

    auto load_stage = [&](int st, int k0) {
        const uint32_t sA = sb + st * STG_BYTES;
#pragma unroll
        for (int i = 0; i < 8; i++) {
            const int id = tid + i * 128;
            const int r = id >> 3, j = id & 7;
            cpa16(sA + r * 128 + ((j ^ (r & 7)) << 4), Ag + (long)r * lda + k0 + j * 4);
        }
        const uint32_t sB = sA + 16384;
#pragma unroll
        for (int i = 0; i < 8; i++) {
            const int id = tid + i * 128;
            const int r = id >> 3, j = id & 7;
            cpa16(sB + r * 128 + ((j ^ (r & 7)) << 4), Bg + (long)r * ldb + k0 + j * 4);
        }
    };

    float acc[4][8][4];
#pragma unroll
    for (int mt = 0; mt < 4; mt++)
#pragma unroll
        for (int nt = 0; nt < 8; nt++)
#pragma unroll
            for (int s = 0; s < 4; s++) acc[mt][nt][s] = 0.f;

    const int r4 = lane >> 2;                 // 0..7 (== row&7 for all fragment rows)
    const int cl = lane & 3;

    const int T = K / 32;
    load_stage(0, 0);
    asm volatile("cp.async.commit_group;" ::: "memory");
    load_stage(1, 32);
    asm volatile("cp.async.commit_group;" ::: "memory");

    for (int t = 0; t < T; t++) {
        asm volatile("cp.async.wait_group 1;" ::: "memory");
        __syncthreads();
        const int u = t + 2;
        if (u < T) load_stage(u % 3, u * 32);
        asm volatile("cp.async.commit_group;" ::: "memory");

        const uint32_t Ab = sb + (t % 3) * STG_BYTES;
        const uint32_t Bb = Ab + 16384;
        const uint32_t aBase = Ab + (wm * 64 + r4) * 128;
        const uint32_t bBase = Bb + (wn * 64 + r4) * 128;
#pragma unroll
        for (int c = 0; c < 2; c++) {
            const uint32_t gs = (uint32_t)((((c << 2) + cl) ^ r4) << 4);
            // A fragments: per mt, two LDS.128 give both kk of this chunk
            uint32_t a0[4][2], a1[4][2], a2[4][2], a3[4][2];
#pragma unroll
            for (int mt = 0; mt < 4; mt++) {
                lds128(aBase + mt * 2048 + gs,
                       a0[mt][0], a2[mt][0], a0[mt][1], a2[mt][1]);
                lds128(aBase + mt * 2048 + 1024 + gs,
                       a1[mt][0], a3[mt][0], a1[mt][1], a3[mt][1]);
            }
            // B fragments: per nt, one LDS.128 gives both kk
            uint32_t b0[8][2], b1[8][2];
#pragma unroll
            for (int nt = 0; nt < 8; nt++)
                lds128(bBase + nt * 1024 + gs,
                       b0[nt][0], b1[nt][0], b0[nt][1], b1[nt][1]);
#pragma unroll
            for (int kk = 0; kk < 2; kk++)
#pragma unroll
                for (int mt = 0; mt < 4; mt++)
#pragma unroll
                    for (int nt = 0; nt < 8; nt++)
                        MMA_TF32(acc[mt][nt], a0[mt][kk], a1[mt][kk],
                                 a2[mt][kk], a3[mt][kk], b0[nt][kk], b1[nt][kk]);
        }
    }

    // ---------------- epilogue ----------------
    float* Cb = C + (long)bz * strideC;
    if (EPI == 1) {
        const int head = (m0 >> 6) + wm;
        const float* aeb = aeT + ((long)bz * HEADS + head) * E_DIM;
        float sc0[8], sc1[8]; int cp0[8], cp1[8];
#pragma unroll
        for (int nt = 0; nt < 8; nt++) {
            const int e = n0 + wn * 64 + nt * 8 + 2 * cl;
            sc0[nt] = aeb[e]; sc1[nt] = aeb[e + 1];
            cp0[nt] = (e & ~15) | perm16(e & 15);
            cp1[nt] = ((e + 1) & ~15) | perm16((e + 1) & 15);
        }
#pragma unroll
        for (int mt = 0; mt < 4; mt++) {
            const int row = m0 + wm * 64 + mt * 16 + r4;
#pragma unroll
            for (int nt = 0; nt < 8; nt++) {
                Cb[(long)row * ldc + cp0[nt]] = rnd(acc[mt][nt][0] * sc0[nt]);
                Cb[(long)row * ldc + cp1[nt]] = rnd(acc[mt][nt][1] * sc1[nt]);
                Cb[(long)(row + 8) * ldc + cp0[nt]] = rnd(acc[mt][nt][2] * sc0[nt]);
                Cb[(long)(row + 8) * ldc + cp1[nt]] = rnd(acc[mt][nt][3] * sc1[nt]);
            }
        }
    } else {
#pragma unroll
        for (int mt = 0; mt < 4; mt++) {
            const int row = m0 + wm * 64 + mt * 16 + r4;
#pragma unroll
            for (int nt = 0; nt < 8; nt++) {
                const int col = n0 + wn * 64 + nt * 8 + 2 * cl;
                float v0 = acc[mt][nt][0], v1 = acc[mt][nt][1];
                float v2 = acc[mt][nt][2], v3 = acc[mt][nt][3];
                if (EPI == 0) { v0 = rnd(v0); v1 = rnd(v1); v2 = rnd(v2); v3 = rnd(v3); }
                float2 o0 = {v0, v1}, o1 = {v2, v3};
                *(float2*)&Cb[(long)row * ldc + col] = o0;
                *(float2*)&Cb[(long)(row + 8) * ldc + col] = o1;
            }
        }
    }
}

// ---------------- prep / transpose kernels ----------------
__global__ __launch_bounds__(256) void prep_x(const float* __restrict__ x) {
    const int i = blockIdx.x * 256 + threadIdx.x;     // float4 id
    const int row = i >> 6, colg = (i & 63) * 4;
    float4 v = ((const float4*)x)[i];
    const float* f = (const float*)&v;
#pragma unroll
    for (int j = 0; j < 4; j++)
        g_xr[(long)row * FIN + (((colg + j) & ~15) | perm16((colg + j) & 15))] = rnd(f[j]);
}
// W (FIN x HD) -> WrT (HD x FIN, k-perm16)
__global__ __launch_bounds__(256) void prep_WT(const float* __restrict__ W) {
    __shared__ float ts[32][33];
    const int o0 = blockIdx.x * 32, i0 = blockIdx.y * 32;
    const int tx = threadIdx.x & 31, ty = threadIdx.x >> 5;
#pragma unroll
    for (int r8 = 0; r8 < 4; r8++) {
        const int il = ty + r8 * 8;
        ts[tx][il] = rnd(W[(long)(i0 + il) * HD + o0 + tx]);
    }
    __syncthreads();
    const int txp = (tx & ~15) | perm16(tx & 15);
#pragma unroll
    for (int r8 = 0; r8 < 4; r8++) {
        const int ol = ty + r8 * 8;
        g_WrT[(long)(o0 + ol) * FIN + i0 + txp] = ts[ol][tx];
    }
}
// H -> Hr (e-perm16) and HT (n-perm16)
__global__ __launch_bounds__(256) void prep_H(const float* __restrict__ H) {
    __shared__ float ts[32][33];
    const int e0 = blockIdx.x * 32, n0 = blockIdx.y * 32;
    const int tx = threadIdx.x & 31, ty = threadIdx.x >> 5;
    const int txp = (tx & ~15) | perm16(tx & 15);
#pragma unroll
    for (int r8 = 0; r8 < 4; r8++) {
        const int nl = ty + r8 * 8;
        const float v = rnd(H[(long)(n0 + nl) * E_DIM + e0 + tx]);
        g_Hr[(long)(n0 + nl) * E_DIM + e0 + txp] = v;
        ts[tx][nl] = v;
    }
    __syncthreads();
#pragma unroll
    for (int r8 = 0; r8 < 4; r8++) {
        const int el = ty + r8 * 8;
        g_HT[(long)(e0 + el) * N_DIM + n0 + txp] = ts[el][tx];
    }
}
// Wh (B*N x HD) -> WhT (B, HD, N n-perm16)
__global__ __launch_bounds__(256) void trWh() {
    __shared__ float ts[32][33];
    const int h0 = blockIdx.x * 32;
    const int n0g = blockIdx.y * 32;
    const int b = n0g >> 13, nn0 = n0g & (N_DIM - 1);
    const int tx = threadIdx.x & 31, ty = threadIdx.x >> 5;
    const int txp = (tx & ~15) | perm16(tx & 15);
#pragma unroll
    for (int r8 = 0; r8 < 4; r8++) {
        const int nl = ty + r8 * 8;
        ts[tx][nl] = g_Wh[(long)(n0g + nl) * HD + h0 + tx];
    }
    __syncthreads();
#pragma unroll
    for (int r8 = 0; r8 < 4; r8++) {
        const int hl = ty + r8 * 8;
        g_WhT[((long)b * HD + h0 + hl) * N_DIM + nn0 + txp] = ts[hl][tx];
    }
}

// ---------------- av / logits / softmax ----------------
__global__ __launch_bounds__(256) void av_kernel(const float* __restrict__ a) {
    const int item = blockIdx.x * 8 + (threadIdx.x >> 5);
    const int lane = threadIdx.x & 31;
    const float* wh = g_Wh + (long)item * DOUT;
    float s = wh[lane] * a[lane] + wh[lane + 32] * a[lane + 32];
#pragma unroll
    for (int o = 16; o; o >>= 1) s += __shfl_xor_sync(0xffffffffu, s, o);
    if (lane == 0) g_av[item] = fmaxf(s, 0.f) + LRELU_ALPHA * fminf(s, 0.f);
}

__global__ __launch_bounds__(256) void logits_kernel(const float* __restrict__ H) {
    const int e = blockIdx.x * 256 + threadIdx.x;
    const int slice = blockIdx.y;
    const int nbeg = slice * (N_DIM / NSLICE);
    float acc[16];
#pragma unroll
    for (int j = 0; j < 16; j++) acc[j] = 0.f;
    __shared__ float avs[64][16];
    for (int nc = 0; nc < N_DIM / NSLICE; nc += 64) {
        __syncthreads();
        for (int i = threadIdx.x; i < 64 * 16; i += 256) {
            const int nn = i >> 4, bh = i & 15;
            avs[nn][bh] = g_av[((long)(bh >> 3) * N_DIM + nbeg + nc + nn) * HEADS + (bh & 7)];
        }
        __syncthreads();
        for (int nn = 0; nn < 64; nn++) {
            const float hv = H[(long)(nbeg + nc + nn) * E_DIM + e];
#pragma unroll
            for (int j = 0; j < 16; j++) acc[j] += hv * avs[nn][j];
        }
    }
#pragma unroll
    for (int j = 0; j < 16; j++)
        g_part[(((long)slice * BATCH + (j >> 3)) * E_DIM + e) * HEADS + (j & 7)] = acc[j];
}

__global__ __launch_bounds__(256) void softmax_kernel() {
    const int bb = blockIdx.x >> 3, hh = blockIdx.x & 7;
    const int t = threadIdx.x;
    float v[E_DIM / 256];
    float mx = -1e30f;
#pragma unroll
    for (int i = 0; i < E_DIM / 256; i++) {
        const int e = i * 256 + t;
        float s = 0.f;
        for (int sl = 0; sl < NSLICE; sl++)
            s += g_part[(((long)sl * BATCH + bb) * E_DIM + e) * HEADS + hh];
        v[i] = s; mx = fmaxf(mx, s);
    }
    __shared__ float red[256];
    red[t] = mx; __syncthreads();
    for (int o = 128; o; o >>= 1) { if (t < o) red[t] = fmaxf(red[t], red[t + o]); __syncthreads(); }
    mx = red[0]; __syncthreads();
    float sum = 0.f;
#pragma unroll
    for (int i = 0; i < E_DIM / 256; i++) { v[i] = __expf(v[i] - mx); sum += v[i]; }
    red[t] = sum; __syncthreads();
    for (int o = 128; o; o >>= 1) { if (t < o) red[t] += red[t + o]; __syncthreads(); }
    const float inv = 1.f / red[0];
#pragma unroll
    for (int i = 0; i < E_DIM / 256; i++)
        g_aeT[((long)bb * HEADS + hh) * E_DIM + i * 256 + t] = v[i] * inv;
}

// ---------------- launch ----------------
extern "C" void kernel_launch(void* const* d_in, const int* in_sizes, int n_in,
                              void* d_out, int out_size)
{
    const float* x = (const float*)d_in[0];
    const float* H = (const float*)d_in[1];
    const float* W = (const float*)d_in[2];
    const float* a = (const float*)d_in[3];
    float* out = (float*)d_out;

    float *pxr, *pWrT, *pHr, *pHT, *pWh, *pWhT, *pm2T, *paeT;
    cudaGetSymbolAddress((void**)&pxr, g_xr);
    cudaGetSymbolAddress((void**)&pWrT, g_WrT);
    cudaGetSymbolAddress((void**)&pHr, g_Hr);
    cudaGetSymbolAddress((void**)&pHT, g_HT);
    cudaGetSymbolAddress((void**)&pWh, g_Wh);
    cudaGetSymbolAddress((void**)&pWhT, g_WhT);
    cudaGetSymbolAddress((void**)&pm2T, g_m2T);
    cudaGetSymbolAddress((void**)&paeT, g_aeT);

    cudaFuncSetAttribute(tgemm<0>, cudaFuncAttributeMaxDynamicSharedMemorySize, SMEM_SZ);
    cudaFuncSetAttribute(tgemm<1>, cudaFuncAttributeMaxDynamicSharedMemorySize, SMEM_SZ);
    cudaFuncSetAttribute(tgemm<2>, cudaFuncAttributeMaxDynamicSharedMemorySize, SMEM_SZ);

    prep_x<<<BATCH * N_DIM * FIN / 4 / 256, 256>>>(x);
    prep_WT<<<dim3(HD / 32, FIN / 32), 256>>>(W);
    prep_H<<<dim3(E_DIM / 32, N_DIM / 32), 256>>>(H);

    // 1) Wh = x @ W : A=xr (16384 x 256), B=WrT (512 x 256) -> Wh natural rounded
    tgemm<0><<<dim3(HD / 128, (BATCH * N_DIM) / 128, 1), 128, SMEM_SZ>>>(
        pxr, pWrT, pWh, FIN, FIN, FIN, HD, 0, 0, 0, nullptr);
    // 2) av + 3) logits + 4) softmax (exact fp32)
    av_kernel<<<BATCH * N_DIM * HEADS / 8, 256>>>(a);
    logits_kernel<<<dim3(E_DIM / 256, NSLICE), 256>>>(H);
    softmax_kernel<<<BATCH * HEADS, 256>>>();
    // transpose Wh -> WhT (n-perm16)
    trWh<<<dim3(HD / 32, BATCH * N_DIM / 32), 256>>>();
    // 5) m2T[b] = ae ⊙ (WhT[b] @ HT^T) : M=HD=512, N=E, K=N_DIM
    tgemm<1><<<dim3(E_DIM / 128, HD / 128, BATCH), 128, SMEM_SZ>>>(
        pWhT, pHT, pm2T, N_DIM, N_DIM, N_DIM, E_DIM,
        (long)HD * N_DIM, 0, (long)HD * E_DIM, paeT);
    // 6) out[b] = Hr @ m2T[b]^T : M=N_DIM, N=HD, K=E
    tgemm<2><<<dim3(HD / 128, N_DIM / 128, BATCH), 128, SMEM_SZ>>>(
        pHr, pm2T, out, E_DIM, E_DIM, E_DIM, HD,
        0, (long)HD * E_DIM, (long)N_DIM * HD, nullptr);
}

// round 7
// speedup vs baseline: 1.1129x; 1.1129x over previous
#include <cuda_runtime.h>
#include <cstdint>

#define E_DIM 4096
#define N_DIM 8192
#define FIN   256
#define HEADS 8
#define DOUT  64
#define HD    512
#define BATCH 2
#define LRELU_ALPHA 0.2f
#define NSLICE 16

// ---------------- scratch ----------------
__device__ __align__(16) float g_xr[BATCH * N_DIM * FIN];    // k-perm8 cols
__device__ __align__(16) float g_WrT[HD * FIN];              // (hd, fin) k-perm8
__device__ __align__(16) float g_Hr[N_DIM * E_DIM];          // e-perm8 cols
__device__ __align__(16) float g_HT[E_DIM * N_DIM];          // n-perm8 cols
__device__ __align__(16) float g_Wh[BATCH * N_DIM * HD];     // natural (rounded)
__device__ __align__(16) float g_WhT[BATCH * HD * N_DIM];    // n-perm8 cols
__device__ __align__(16) float g_m2T[BATCH * HD * E_DIM];    // e-perm8 cols (rounded, ae-scaled)
__device__ float g_av[BATCH * N_DIM * HEADS];
__device__ float g_part[NSLICE * BATCH * E_DIM * HEADS];
__device__ float g_aeT[BATCH * HEADS * E_DIM];

__device__ __forceinline__ uint32_t f2tf32(float f) {
    uint32_t r; asm("cvt.rna.tf32.f32 %0, %1;" : "=r"(r) : "f"(f)); return r;
}
__device__ __forceinline__ float rnd(float f) { return __uint_as_float(f2tf32(f)); }
__device__ __forceinline__ uint32_t smem_u32(const void* p) {
    uint32_t a;
    asm("{ .reg .u64 t; cvta.to.shared.u64 t, %1; cvt.u32.u64 %0, t; }" : "=r"(a) : "l"(p));
    return a;
}
__device__ __forceinline__ void lds64(uint32_t a, uint32_t& x, uint32_t& y) {
    asm volatile("ld.shared.v2.b32 {%0,%1}, [%2];" : "=r"(x), "=r"(y) : "r"(a));
}
__device__ __forceinline__ void cpa16(uint32_t dst, const void* src) {
    asm volatile("cp.async.cg.shared.global [%0], [%1], 16;" :: "r"(dst), "l"(src));
}
__device__ __host__ __forceinline__ int perm8(int k) { return ((k & 3) << 1) | ((k >> 2) & 1); }

#define MMA_TF32(c, a, b) \
    asm volatile("mma.sync.aligned.m16n8k8.row.col.f32.tf32.tf32.f32 " \
        "{%0,%1,%2,%3}, {%4,%5,%6,%7}, {%8,%9}, {%0,%1,%2,%3};" \
        : "+f"((c)[0]), "+f"((c)[1]), "+f"((c)[2]), "+f"((c)[3]) \
        : "r"((a)[0]), "r"((a)[1]), "r"((a)[2]), "r"((a)[3]), \
          "r"((b)[0]), "r"((b)[1]))

#define STG_BYTES 49152               // A 16KB (128 rows) + B 32KB (256 rows), 128B/row
#define STAGES 3
#define SMEM_SZ (STAGES * STG_BYTES)  // 144 KB

// ---------------- tf32 mma GEMM: CTA 128(M)x256(N), 8 warps (64x64 each), K-step 32 ------
// A: (M x K) rows m, k-perm8 cols.  B: (N x K) rows n, k-perm8 cols.  C: (M x N) row-major.
// EPI 0: round + fused av (aeT = a_vertices)
// EPI 1: scale by aeT[bz,head(row),e(col)] + round + perm8-col store
// EPI 2: plain
template<int EPI>
__global__ void __launch_bounds__(256, 1) tgemm(
    const float* __restrict__ A, const float* __restrict__ B, float* __restrict__ C,
    int K, int lda, int ldb, int ldc,
    long strideA, long strideB, long strideC, const float* __restrict__ aeT)
{
    extern __shared__ char smem[];
    const uint32_t sb = smem_u32(smem);
    const int tid = threadIdx.x, lane = tid & 31, wid = tid >> 5;
    const int wm = wid >> 2, wn = wid & 3;           // 2 x 4 warps
    const int m0 = blockIdx.y * 128, n0 = blockIdx.x * 256, bz = blockIdx.z;

    const float* Ag = A + (long)bz * strideA + (long)m0 * lda;
    const float* Bg = B + (long)bz * strideB + (long)n0 * ldb;

    auto load_stage = [&](int st, int k0) {
        const uint32_t sA = sb + st * STG_BYTES;
#pragma unroll
        for (int i = 0; i < 4; i++) {                 // 128 rows x 8 groups
            const int id = tid + i * 256;
            const int r = id >> 3, j = id & 7;
            cpa16(sA + r * 128 + ((j ^ ((r & 3) << 1)) << 4), Ag + (long)r * lda + k0 + j * 4);
        }
        const uint32_t sB = sA + 16384;
#pragma unroll
        for (int i = 0; i < 8; i++) {                 // 256 rows x 8 groups
            const int id = tid + i * 256;
            const int r = id >> 3, j = id & 7;
            cpa16(sB + r * 128 + ((j ^ ((r & 3) << 1)) << 4), Bg + (long)r * ldb + k0 + j * 4);
        }
    };

    float acc[4][8][4];
#pragma unroll
    for (int mt = 0; mt < 4; mt++)
#pragma unroll
        for (int nt = 0; nt < 8; nt++)
#pragma unroll
            for (int s = 0; s < 4; s++) acc[mt][nt][s] = 0.f;

    const int r4 = lane >> 2;                 // 0..7
    const int cl = lane & 3;
    const int swz = (r4 & 3) << 1;
    const int c2 = cl >> 1;
    const int hof = (cl & 1) * 8;

    uint32_t af[2][4][4], bf[2][8][2];

    const int T = K / 32;
    load_stage(0, 0);
    asm volatile("cp.async.commit_group;" ::: "memory");
    load_stage(1, 32);
    asm volatile("cp.async.commit_group;" ::: "memory");

    for (int t = 0; t < T; t++) {
        asm volatile("cp.async.wait_group 1;" ::: "memory");
        __syncthreads();
        const int u = t + 2;
        if (u < T) load_stage(u % 3, u * 32);
        asm volatile("cp.async.commit_group;" ::: "memory");

        const uint32_t Ab = sb + (t % 3) * STG_BYTES;
        const uint32_t Bb = Ab + 16384;
        const uint32_t aBase = Ab + (wm * 64 + r4) * 128 + hof;
        const uint32_t bBase = Bb + (wn * 64 + r4) * 128 + hof;

        auto ldfrag = [&](int bufi, int kk) {
            const uint32_t gsb = (uint32_t)(((kk * 2 + c2) ^ swz) << 4);
#pragma unroll
            for (int mt = 0; mt < 4; mt++) {
                lds64(aBase + mt * 2048 + gsb, af[bufi][mt][0], af[bufi][mt][2]);
                lds64(aBase + mt * 2048 + 1024 + gsb, af[bufi][mt][1], af[bufi][mt][3]);
            }
#pragma unroll
            for (int nt = 0; nt < 8; nt++)
                lds64(bBase + nt * 1024 + gsb, bf[bufi][nt][0], bf[bufi][nt][1]);
        };

        ldfrag(0, 0);
#pragma unroll
        for (int kk = 0; kk < 4; kk++) {
            if (kk < 3) ldfrag((kk + 1) & 1, kk + 1);
            const int cb = kk & 1;
#pragma unroll
            for (int mt = 0; mt < 4; mt++)
#pragma unroll
                for (int nt = 0; nt < 8; nt++)
                    MMA_TF32(acc[mt][nt], af[cb][mt], bf[cb][nt]);
        }
    }

    // ---------------- epilogue ----------------
    float* Cb = C + (long)bz * strideC;
    if (EPI == 0) {
        // round + store + fused av = leaky(sum_d Wh*a)  (aeT = a_vertices, len 64)
        const int head = (n0 >> 6) + wn;
        float aw0[8], aw1[8];
#pragma unroll
        for (int nt = 0; nt < 8; nt++) {
            aw0[nt] = aeT[nt * 8 + 2 * cl];
            aw1[nt] = aeT[nt * 8 + 2 * cl + 1];
        }
#pragma unroll
        for (int mt = 0; mt < 4; mt++) {
            const int row = m0 + wm * 64 + mt * 16 + r4;
            float s0 = 0.f, s1 = 0.f;
#pragma unroll
            for (int nt = 0; nt < 8; nt++) {
                const int col = n0 + wn * 64 + nt * 8 + 2 * cl;
                const float v0 = rnd(acc[mt][nt][0]), v1 = rnd(acc[mt][nt][1]);
                const float v2 = rnd(acc[mt][nt][2]), v3 = rnd(acc[mt][nt][3]);
                float2 o0 = {v0, v1}, o1 = {v2, v3};
                *(float2*)&Cb[(long)row * ldc + col] = o0;
                *(float2*)&Cb[(long)(row + 8) * ldc + col] = o1;
                s0 += v0 * aw0[nt] + v1 * aw1[nt];
                s1 += v2 * aw0[nt] + v3 * aw1[nt];
            }
            s0 += __shfl_xor_sync(0xffffffffu, s0, 1);
            s0 += __shfl_xor_sync(0xffffffffu, s0, 2);
            s1 += __shfl_xor_sync(0xffffffffu, s1, 1);
            s1 += __shfl_xor_sync(0xffffffffu, s1, 2);
            if (cl == 0) {
                g_av[(long)row * HEADS + head] =
                    fmaxf(s0, 0.f) + LRELU_ALPHA * fminf(s0, 0.f);
                g_av[(long)(row + 8) * HEADS + head] =
                    fmaxf(s1, 0.f) + LRELU_ALPHA * fminf(s1, 0.f);
            }
        }
    } else if (EPI == 1) {
        const int head = (m0 >> 6) + wm;
        const float* aeb = aeT + ((long)bz * HEADS + head) * E_DIM;
        float sc0[8], sc1[8]; int cp0[8], cp1[8];
#pragma unroll
        for (int nt = 0; nt < 8; nt++) {
            const int e = n0 + wn * 64 + nt * 8 + 2 * cl;
            sc0[nt] = aeb[e]; sc1[nt] = aeb[e + 1];
            cp0[nt] = (e & ~7) | perm8(e & 7);
            cp1[nt] = (e & ~7) | perm8((e & 7) + 1);
        }
#pragma unroll
        for (int mt = 0; mt < 4; mt++) {
            const int row = m0 + wm * 64 + mt * 16 + r4;
#pragma unroll
            for (int nt = 0; nt < 8; nt++) {
                Cb[(long)row * ldc + cp0[nt]] = rnd(acc[mt][nt][0] * sc0[nt]);
                Cb[(long)row * ldc + cp1[nt]] = rnd(acc[mt][nt][1] * sc1[nt]);
                Cb[(long)(row + 8) * ldc + cp0[nt]] = rnd(acc[mt][nt][2] * sc0[nt]);
                Cb[(long)(row + 8) * ldc + cp1[nt]] = rnd(acc[mt][nt][3] * sc1[nt]);
            }
        }
    } else {
#pragma unroll
        for (int mt = 0; mt < 4; mt++) {
            const int row = m0 + wm * 64 + mt * 16 + r4;
#pragma unroll
            for (int nt = 0; nt < 8; nt++) {
                const int col = n0 + wn * 64 + nt * 8 + 2 * cl;
                float2 o0 = {acc[mt][nt][0], acc[mt][nt][1]};
                float2 o1 = {acc[mt][nt][2], acc[mt][nt][3]};
                *(float2*)&Cb[(long)row * ldc + col] = o0;
                *(float2*)&Cb[(long)(row + 8) * ldc + col] = o1;
            }
        }
    }
}

// ---------------- prep / transpose kernels (perm8) ----------------
__global__ __launch_bounds__(256) void prep_x(const float* __restrict__ x) {
    const int i = blockIdx.x * 256 + threadIdx.x;
    const int row = i >> 6, colg = (i & 63) * 4;
    float4 v = ((const float4*)x)[i];
    const float* f = (const float*)&v;
#pragma unroll
    for (int j = 0; j < 4; j++)
        g_xr[(long)row * FIN + (((colg + j) & ~7) | perm8((colg + j) & 7))] = rnd(f[j]);
}
__global__ __launch_bounds__(256) void prep_WT(const float* __restrict__ W) {
    __shared__ float ts[32][33];
    const int o0 = blockIdx.x * 32, i0 = blockIdx.y * 32;
    const int tx = threadIdx.x & 31, ty = threadIdx.x >> 5;
#pragma unroll
    for (int r8 = 0; r8 < 4; r8++) {
        const int il = ty + r8 * 8;
        ts[tx][il] = rnd(W[(long)(i0 + il) * HD + o0 + tx]);
    }
    __syncthreads();
    const int txp = (tx & ~7) | perm8(tx & 7);
#pragma unroll
    for (int r8 = 0; r8 < 4; r8++) {
        const int ol = ty + r8 * 8;
        g_WrT[(long)(o0 + ol) * FIN + i0 + txp] = ts[ol][tx];
    }
}
__global__ __launch_bounds__(256) void prep_H(const float* __restrict__ H) {
    __shared__ float ts[32][33];
    const int e0 = blockIdx.x * 32, n0 = blockIdx.y * 32;
    const int tx = threadIdx.x & 31, ty = threadIdx.x >> 5;
    const int txp = (tx & ~7) | perm8(tx & 7);
#pragma unroll
    for (int r8 = 0; r8 < 4; r8++) {
        const int nl = ty + r8 * 8;
        const float v = rnd(H[(long)(n0 + nl) * E_DIM + e0 + tx]);
        g_Hr[(long)(n0 + nl) * E_DIM + e0 + txp] = v;
        ts[tx][nl] = v;
    }
    __syncthreads();
#pragma unroll
    for (int r8 = 0; r8 < 4; r8++) {
        const int el = ty + r8 * 8;
        g_HT[(long)(e0 + el) * N_DIM + n0 + txp] = ts[el][tx];
    }
}
__global__ __launch_bounds__(256) void trWh() {
    __shared__ float ts[32][33];
    const int h0 = blockIdx.x * 32;
    const int n0g = blockIdx.y * 32;
    const int b = n0g >> 13, nn0 = n0g & (N_DIM - 1);
    const int tx = threadIdx.x & 31, ty = threadIdx.x >> 5;
    const int txp = (tx & ~7) | perm8(tx & 7);
#pragma unroll
    for (int r8 = 0; r8 < 4; r8++) {
        const int nl = ty + r8 * 8;
        ts[tx][nl] = g_Wh[(long)(n0g + nl) * HD + h0 + tx];
    }
    __syncthreads();
#pragma unroll
    for (int r8 = 0; r8 < 4; r8++) {
        const int hl = ty + r8 * 8;
        g_WhT[((long)b * HD + h0 + hl) * N_DIM + nn0 + txp] = ts[hl][tx];
    }
}

// ---------------- logits / softmax ----------------
__global__ __launch_bounds__(256) void logits_kernel(const float* __restrict__ H) {
    const int e = blockIdx.x * 256 + threadIdx.x;
    const int slice = blockIdx.y;
    const int nbeg = slice * (N_DIM / NSLICE);
    float acc[16];
#pragma unroll
    for (int j = 0; j < 16; j++) acc[j] = 0.f;
    __shared__ float avs[64][16];
    for (int nc = 0; nc < N_DIM / NSLICE; nc += 64) {
        __syncthreads();
        for (int i = threadIdx.x; i < 64 * 16; i += 256) {
            const int nn = i >> 4, bh = i & 15;
            avs[nn][bh] = g_av[((long)(bh >> 3) * N_DIM + nbeg + nc + nn) * HEADS + (bh & 7)];
        }
        __syncthreads();
        for (int nn = 0; nn < 64; nn++) {
            const float hv = H[(long)(nbeg + nc + nn) * E_DIM + e];
#pragma unroll
            for (int j = 0; j < 16; j++) acc[j] += hv * avs[nn][j];
        }
    }
#pragma unroll
    for (int j = 0; j < 16; j++)
        g_part[(((long)slice * BATCH + (j >> 3)) * E_DIM + e) * HEADS + (j & 7)] = acc[j];
}

__global__ __launch_bounds__(256) void softmax_kernel() {
    const int bb = blockIdx.x >> 3, hh = blockIdx.x & 7;
    const int t = threadIdx.x;
    float v[E_DIM / 256];
    float mx = -1e30f;
#pragma unroll
    for (int i = 0; i < E_DIM / 256; i++) {
        const int e = i * 256 + t;
        float s = 0.f;
        for (int sl = 0; sl < NSLICE; sl++)
            s += g_part[(((long)sl * BATCH + bb) * E_DIM + e) * HEADS + hh];
        v[i] = s; mx = fmaxf(mx, s);
    }
    __shared__ float red[256];
    red[t] = mx; __syncthreads();
    for (int o = 128; o; o >>= 1) { if (t < o) red[t] = fmaxf(red[t], red[t + o]); __syncthreads(); }
    mx = red[0]; __syncthreads();
    float sum = 0.f;
#pragma unroll
    for (int i = 0; i < E_DIM / 256; i++) { v[i] = __expf(v[i] - mx); sum += v[i]; }
    red[t] = sum; __syncthreads();
    for (int o = 128; o; o >>= 1) { if (t < o) red[t] += red[t + o]; __syncthreads(); }
    const float inv = 1.f / red[0];
#pragma unroll
    for (int i = 0; i < E_DIM / 256; i++)
        g_aeT[((long)bb * HEADS + hh) * E_DIM + i * 256 + t] = v[i] * inv;
}

// ---------------- launch ----------------
extern "C" void kernel_launch(void* const* d_in, const int* in_sizes, int n_in,
                              void* d_out, int out_size)
{
    const float* x = (const float*)d_in[0];
    const float* H = (const float*)d_in[1];
    const float* W = (const float*)d_in[2];
    const float* a = (const float*)d_in[3];
    float* out = (float*)d_out;

    float *pxr, *pWrT, *pHr, *pHT, *pWh, *pWhT, *pm2T, *paeT;
    cudaGetSymbolAddress((void**)&pxr, g_xr);
    cudaGetSymbolAddress((void**)&pWrT, g_WrT);
    cudaGetSymbolAddress((void**)&pHr, g_Hr);
    cudaGetSymbolAddress((void**)&pHT, g_HT);
    cudaGetSymbolAddress((void**)&pWh, g_Wh);
    cudaGetSymbolAddress((void**)&pWhT, g_WhT);
    cudaGetSymbolAddress((void**)&pm2T, g_m2T);
    cudaGetSymbolAddress((void**)&paeT, g_aeT);

    cudaFuncSetAttribute(tgemm<0>, cudaFuncAttributeMaxDynamicSharedMemorySize, SMEM_SZ);
    cudaFuncSetAttribute(tgemm<1>, cudaFuncAttributeMaxDynamicSharedMemorySize, SMEM_SZ);
    cudaFuncSetAttribute(tgemm<2>, cudaFuncAttributeMaxDynamicSharedMemorySize, SMEM_SZ);

    prep_x<<<BATCH * N_DIM * FIN / 4 / 256, 256>>>(x);
    prep_WT<<<dim3(HD / 32, FIN / 32), 256>>>(W);
    prep_H<<<dim3(E_DIM / 32, N_DIM / 32), 256>>>(H);

    // 1) Wh = x @ W (+ fused av) : M=16384 flat, N=512, K=256
    tgemm<0><<<dim3(HD / 256, (BATCH * N_DIM) / 128, 1), 256, SMEM_SZ>>>(
        pxr, pWrT, pWh, FIN, FIN, FIN, HD, 0, 0, 0, a);
    // 3) logits + 4) softmax (exact fp32)
    logits_kernel<<<dim3(E_DIM / 256, NSLICE), 256>>>(H);
    softmax_kernel<<<BATCH * HEADS, 256>>>();
    // transpose Wh -> WhT (n-perm8)
    trWh<<<dim3(HD / 32, BATCH * N_DIM / 32), 256>>>();
    // 5) m2T[b] = ae ⊙ (WhT[b] @ HT^T) : M=HD=512, N=E, K=N_DIM
    tgemm<1><<<dim3(E_DIM / 256, HD / 128, BATCH), 256, SMEM_SZ>>>(
        pWhT, pHT, pm2T, N_DIM, N_DIM, N_DIM, E_DIM,
        (long)HD * N_DIM, 0, (long)HD * E_DIM, paeT);
    // 6) out[b] = Hr @ m2T[b]^T : M=N_DIM, N=HD, K=E
    tgemm<2><<<dim3(HD / 256, N_DIM / 128, BATCH), 256, SMEM_SZ>>>(
        pHr, pm2T, out, E_DIM, E_DIM, E_DIM, HD,
        0, (long)HD * E_DIM, (long)N_DIM * HD, nullptr);
}

// round 8
// speedup vs baseline: 1.8447x; 1.6576x over previous
#include <cuda_runtime.h>
#include <cuda_fp16.h>
#include <cstdint>

#define E_DIM 4096
#define N_DIM 8192
#define FIN   256
#define HEADS 8
#define DOUT  64
#define HD    512
#define BATCH 2
#define LRELU_ALPHA 0.2f
#define NSLICE 16

// ---------------- scratch (fp16 operands, k-perm16h columns) ----------------
__device__ __align__(16) __half g_x16[BATCH * N_DIM * FIN];
__device__ __align__(16) __half g_W16T[HD * FIN];
__device__ __align__(16) __half g_Hr16[N_DIM * E_DIM];     // (n, e-perm)
__device__ __align__(16) __half g_HT16[E_DIM * N_DIM];     // (e, n-perm)
__device__ __align__(16) __half g_Wh16[BATCH * N_DIM * HD];  // natural
__device__ __align__(16) __half g_WhT16[BATCH * HD * N_DIM]; // (hd, n-perm)
__device__ __align__(16) __half g_m2T16[BATCH * HD * E_DIM]; // (hd, e-perm), ae-scaled
__device__ float g_av[BATCH * N_DIM * HEADS];
__device__ float g_part[NSLICE * BATCH * E_DIM * HEADS];
__device__ float g_aeT[BATCH * HEADS * E_DIM];

__device__ __forceinline__ uint32_t smem_u32(const void* p) {
    uint32_t a;
    asm("{ .reg .u64 t; cvta.to.shared.u64 t, %1; cvt.u32.u64 %0, t; }" : "=r"(a) : "l"(p));
    return a;
}
__device__ __forceinline__ void lds64(uint32_t a, uint32_t& x, uint32_t& y) {
    asm volatile("ld.shared.v2.b32 {%0,%1}, [%2];" : "=r"(x), "=r"(y) : "r"(a));
}
__device__ __forceinline__ void cpa16(uint32_t dst, const void* src) {
    asm volatile("cp.async.cg.shared.global [%0], [%1], 16;" :: "r"(dst), "l"(src));
}
// within-16 k permutation: k -> ((k&6)<<1) | (((k>>3)&1)<<1) | (k&1)
// places the mma quad {2c,2c+1,2c+8,2c+9} at contiguous positions 4c..4c+3.
__device__ __host__ __forceinline__ int perm16h(int k) {
    return ((k & 6) << 1) | (((k >> 3) & 1) << 1) | (k & 1);
}

#define MMA_F16(c, a, b) \
    asm volatile("mma.sync.aligned.m16n8k16.row.col.f32.f16.f16.f32 " \
        "{%0,%1,%2,%3}, {%4,%5,%6,%7}, {%8,%9}, {%0,%1,%2,%3};" \
        : "+f"((c)[0]), "+f"((c)[1]), "+f"((c)[2]), "+f"((c)[3]) \
        : "r"((a)[0]), "r"((a)[1]), "r"((a)[2]), "r"((a)[3]), \
          "r"((b)[0]), "r"((b)[1]))

#define STG_BYTES 32768               // A 16KB + B 16KB (128 rows x 128B, 64 fp16/row)
#define STAGES 3
#define SMEM_SZ (STAGES * STG_BYTES)  // 96 KB

// ---------------- fp16 mma GEMM: CTA 128x128, 4 warps (64x64), K-step 64 ----------------
// A: (M x K) fp16, k-perm16h cols.  B: (N x K) fp16, k-perm16h cols.
// EPI 0: store fp16 natural + fused av (aeT = a_vertices)
// EPI 1: scale by aeT[bz,head(row),e(col)], fp16 store with perm16h cols
// EPI 2: fp32 plain store
template<int EPI>
__global__ void __launch_bounds__(128, 2) hgemm(
    const __half* __restrict__ A, const __half* __restrict__ B, void* __restrict__ Cv,
    int K, int lda, int ldb, int ldc,
    long strideA, long strideB, long strideC, const float* __restrict__ aeT)
{
    extern __shared__ char smem[];
    const uint32_t sb = smem_u32(smem);
    const int tid = threadIdx.x, lane = tid & 31, wid = tid >> 5;
    const int wm = wid >> 1, wn = wid & 1;
    const int m0 = blockIdx.y * 128, n0 = blockIdx.x * 128, bz = blockIdx.z;

    const __half* Ag = A + (long)bz * strideA + (long)m0 * lda;
    const __half* Bg = B + (long)bz * strideB + (long)n0 * ldb;

    auto load_stage = [&](int st, int k0) {
        const uint32_t sA = sb + st * STG_BYTES;
#pragma unroll
        for (int i = 0; i < 8; i++) {
            const int id = tid + i * 128;
            const int r = id >> 3, j = id & 7;
            cpa16(sA + r * 128 + ((j ^ ((r & 3) << 1)) << 4), Ag + (long)r * lda + k0 + j * 8);
        }
        const uint32_t sB = sA + 16384;
#pragma unroll
        for (int i = 0; i < 8; i++) {
            const int id = tid + i * 128;
            const int r = id >> 3, j = id & 7;
            cpa16(sB + r * 128 + ((j ^ ((r & 3) << 1)) << 4), Bg + (long)r * ldb + k0 + j * 8);
        }
    };

    float acc[4][8][4];
#pragma unroll
    for (int mt = 0; mt < 4; mt++)
#pragma unroll
        for (int nt = 0; nt < 8; nt++)
#pragma unroll
            for (int s = 0; s < 4; s++) acc[mt][nt][s] = 0.f;

    const int r4 = lane >> 2;
    const int cl = lane & 3;
    const int swz = (r4 & 3) << 1;
    const int c2 = cl >> 1;
    const int hof = (cl & 1) * 8;

    const int T = K / 64;
    load_stage(0, 0);
    asm volatile("cp.async.commit_group;" ::: "memory");
    load_stage(1, 64);
    asm volatile("cp.async.commit_group;" ::: "memory");

    for (int t = 0; t < T; t++) {
        asm volatile("cp.async.wait_group 1;" ::: "memory");
        __syncthreads();
        const int u = t + 2;
        if (u < T) load_stage(u % 3, u * 64);
        asm volatile("cp.async.commit_group;" ::: "memory");

        const uint32_t Ab = sb + (t % 3) * STG_BYTES;
        const uint32_t Bb = Ab + 16384;
        const uint32_t aBase = Ab + (wm * 64 + r4) * 128 + hof;
        const uint32_t bBase = Bb + (wn * 64 + r4) * 128 + hof;
#pragma unroll
        for (int kk = 0; kk < 4; kk++) {          // each kk = K=16
            const uint32_t gsb = (uint32_t)(((kk * 2 + c2) ^ swz) << 4);
            uint32_t af[4][4], bf[8][2];
#pragma unroll
            for (int mt = 0; mt < 4; mt++) {
                lds64(aBase + mt * 2048 + gsb, af[mt][0], af[mt][2]);
                lds64(aBase + mt * 2048 + 1024 + gsb, af[mt][1], af[mt][3]);
            }
#pragma unroll
            for (int nt = 0; nt < 8; nt++)
                lds64(bBase + nt * 1024 + gsb, bf[nt][0], bf[nt][1]);
#pragma unroll
            for (int mt = 0; mt < 4; mt++)
#pragma unroll
                for (int nt = 0; nt < 8; nt++)
                    MMA_F16(acc[mt][nt], af[mt], bf[nt]);
        }
    }

    // ---------------- epilogue ----------------
    if (EPI == 0) {
        __half* Cb = (__half*)Cv;                 // flat (B*N) x HD
        const int head = (n0 >> 6) + wn;
        float aw0[8], aw1[8];
#pragma unroll
        for (int nt = 0; nt < 8; nt++) {
            aw0[nt] = aeT[nt * 8 + 2 * cl];
            aw1[nt] = aeT[nt * 8 + 2 * cl + 1];
        }
#pragma unroll
        for (int mt = 0; mt < 4; mt++) {
            const int row = m0 + wm * 64 + mt * 16 + r4;
            float s0 = 0.f, s1 = 0.f;
#pragma unroll
            for (int nt = 0; nt < 8; nt++) {
                const int col = n0 + wn * 64 + nt * 8 + 2 * cl;
                const __half h0 = __float2half_rn(acc[mt][nt][0]);
                const __half h1 = __float2half_rn(acc[mt][nt][1]);
                const __half h2 = __float2half_rn(acc[mt][nt][2]);
                const __half h3 = __float2half_rn(acc[mt][nt][3]);
                *(__half2*)&Cb[(long)row * ldc + col] = __halves2half2(h0, h1);
                *(__half2*)&Cb[(long)(row + 8) * ldc + col] = __halves2half2(h2, h3);
                s0 += __half2float(h0) * aw0[nt] + __half2float(h1) * aw1[nt];
                s1 += __half2float(h2) * aw0[nt] + __half2float(h3) * aw1[nt];
            }
            s0 += __shfl_xor_sync(0xffffffffu, s0, 1);
            s0 += __shfl_xor_sync(0xffffffffu, s0, 2);
            s1 += __shfl_xor_sync(0xffffffffu, s1, 1);
            s1 += __shfl_xor_sync(0xffffffffu, s1, 2);
            if (cl == 0) {
                g_av[(long)row * HEADS + head] =
                    fmaxf(s0, 0.f) + LRELU_ALPHA * fminf(s0, 0.f);
                g_av[(long)(row + 8) * HEADS + head] =
                    fmaxf(s1, 0.f) + LRELU_ALPHA * fminf(s1, 0.f);
            }
        }
    } else if (EPI == 1) {
        __half* Cb = (__half*)Cv + (long)bz * strideC;
        const int head = (m0 >> 6) + wm;
        const float* aeb = aeT + ((long)bz * HEADS + head) * E_DIM;
        float sc0[8], sc1[8]; int cp[8];
#pragma unroll
        for (int nt = 0; nt < 8; nt++) {
            const int e = n0 + wn * 64 + nt * 8 + 2 * cl;   // even
            sc0[nt] = aeb[e]; sc1[nt] = aeb[e + 1];
            cp[nt] = (e & ~15) | perm16h(e & 15);           // cp+1 holds e+1
        }
#pragma unroll
        for (int mt = 0; mt < 4; mt++) {
            const int row = m0 + wm * 64 + mt * 16 + r4;
#pragma unroll
            for (int nt = 0; nt < 8; nt++) {
                *(__half2*)&Cb[(long)row * ldc + cp[nt]] = __halves2half2(
                    __float2half_rn(acc[mt][nt][0] * sc0[nt]),
                    __float2half_rn(acc[mt][nt][1] * sc1[nt]));
                *(__half2*)&Cb[(long)(row + 8) * ldc + cp[nt]] = __halves2half2(
                    __float2half_rn(acc[mt][nt][2] * sc0[nt]),
                    __float2half_rn(acc[mt][nt][3] * sc1[nt]));
            }
        }
    } else {
        float* Cb = (float*)Cv + (long)bz * strideC;
#pragma unroll
        for (int mt = 0; mt < 4; mt++) {
            const int row = m0 + wm * 64 + mt * 16 + r4;
#pragma unroll
            for (int nt = 0; nt < 8; nt++) {
                const int col = n0 + wn * 64 + nt * 8 + 2 * cl;
                float2 o0 = {acc[mt][nt][0], acc[mt][nt][1]};
                float2 o1 = {acc[mt][nt][2], acc[mt][nt][3]};
                *(float2*)&Cb[(long)row * ldc + col] = o0;
                *(float2*)&Cb[(long)(row + 8) * ldc + col] = o1;
            }
        }
    }
}

// ---------------- prep kernels ----------------
// generic: fp32 row-major -> fp16 with perm16h applied within each 16-col block
__global__ __launch_bounds__(256) void prep_pack(const float* __restrict__ src,
                                                 __half* __restrict__ dst) {
    const long idx = (long)blockIdx.x * 256 + threadIdx.x;   // 16-elem block id
    float f[16];
#pragma unroll
    for (int q = 0; q < 4; q++) {
        float4 v = ((const float4*)src)[idx * 4 + q];
        f[q * 4 + 0] = v.x; f[q * 4 + 1] = v.y; f[q * 4 + 2] = v.z; f[q * 4 + 3] = v.w;
    }
    __align__(16) __half hp[16];
#pragma unroll
    for (int k = 0; k < 16; k++) hp[perm16h(k)] = __float2half_rn(f[k]);
    ((uint4*)dst)[idx * 2] = ((const uint4*)hp)[0];
    ((uint4*)dst)[idx * 2 + 1] = ((const uint4*)hp)[1];
}
// W (FIN x HD) -> W16T (HD x FIN, k-perm16h)
__global__ __launch_bounds__(256) void prep_WT(const float* __restrict__ W) {
    __shared__ float ts[32][33];
    const int o0 = blockIdx.x * 32, i0 = blockIdx.y * 32;
    const int tx = threadIdx.x & 31, ty = threadIdx.x >> 5;
#pragma unroll
    for (int r8 = 0; r8 < 4; r8++) {
        const int il = ty + r8 * 8;
        ts[tx][il] = W[(long)(i0 + il) * HD + o0 + tx];
    }
    __syncthreads();
    const int txp = (tx & ~15) | perm16h(tx & 15);
#pragma unroll
    for (int r8 = 0; r8 < 4; r8++) {
        const int ol = ty + r8 * 8;
        g_W16T[(long)(o0 + ol) * FIN + i0 + txp] = __float2half_rn(ts[ol][tx]);
    }
}
// H (N x E) -> HT16 (E x N, n-perm16h)
__global__ __launch_bounds__(256) void prep_HT(const float* __restrict__ H) {
    __shared__ float ts[32][33];
    const int e0 = blockIdx.x * 32, n0 = blockIdx.y * 32;
    const int tx = threadIdx.x & 31, ty = threadIdx.x >> 5;
#pragma unroll
    for (int r8 = 0; r8 < 4; r8++) {
        const int nl = ty + r8 * 8;
        ts[tx][nl] = H[(long)(n0 + nl) * E_DIM + e0 + tx];   // ts[e_l][n_l]
    }
    __syncthreads();
    const int txp = (tx & ~15) | perm16h(tx & 15);
#pragma unroll
    for (int r8 = 0; r8 < 4; r8++) {
        const int el = ty + r8 * 8;
        g_HT16[(long)(e0 + el) * N_DIM + n0 + txp] = __float2half_rn(ts[el][tx]);
    }
}
// Wh16 (B*N x HD) -> WhT16 (B, HD, N n-perm16h)
__global__ __launch_bounds__(256) void trWh() {
    __shared__ __half ts[32][34];
    const int h0 = blockIdx.x * 32;
    const int n0g = blockIdx.y * 32;
    const int b = n0g >> 13, nn0 = n0g & (N_DIM - 1);
    const int tx = threadIdx.x & 31, ty = threadIdx.x >> 5;
#pragma unroll
    for (int r8 = 0; r8 < 4; r8++) {
        const int nl = ty + r8 * 8;
        ts[tx][nl] = g_Wh16[(long)(n0g + nl) * HD + h0 + tx];  // ts[hd_l][n_l]
    }
    __syncthreads();
    const int txp = (tx & ~15) | perm16h(tx & 15);
#pragma unroll
    for (int r8 = 0; r8 < 4; r8++) {
        const int hl = ty + r8 * 8;
        g_WhT16[((long)b * HD + h0 + hl) * N_DIM + nn0 + txp] = ts[hl][tx];
    }
}

// ---------------- logits / softmax (exact fp32) ----------------
__global__ __launch_bounds__(256) void logits_kernel(const float* __restrict__ H) {
    const int e = blockIdx.x * 256 + threadIdx.x;
    const int slice = blockIdx.y;
    const int nbeg = slice * (N_DIM / NSLICE);
    float acc[16];
#pragma unroll
    for (int j = 0; j < 16; j++) acc[j] = 0.f;
    __shared__ float avs[64][16];
    for (int nc = 0; nc < N_DIM / NSLICE; nc += 64) {
        __syncthreads();
        for (int i = threadIdx.x; i < 64 * 16; i += 256) {
            const int nn = i >> 4, bh = i & 15;
            avs[nn][bh] = g_av[((long)(bh >> 3) * N_DIM + nbeg + nc + nn) * HEADS + (bh & 7)];
        }
        __syncthreads();
        for (int nn = 0; nn < 64; nn++) {
            const float hv = H[(long)(nbeg + nc + nn) * E_DIM + e];
#pragma unroll
            for (int j = 0; j < 16; j++) acc[j] += hv * avs[nn][j];
        }
    }
#pragma unroll
    for (int j = 0; j < 16; j++)
        g_part[(((long)slice * BATCH + (j >> 3)) * E_DIM + e) * HEADS + (j & 7)] = acc[j];
}

__global__ __launch_bounds__(256) void softmax_kernel() {
    const int bb = blockIdx.x >> 3, hh = blockIdx.x & 7;
    const int t = threadIdx.x;
    float v[E_DIM / 256];
    float mx = -1e30f;
#pragma unroll
    for (int i = 0; i < E_DIM / 256; i++) {
        const int e = i * 256 + t;
        float s = 0.f;
        for (int sl = 0; sl < NSLICE; sl++)
            s += g_part[(((long)sl * BATCH + bb) * E_DIM + e) * HEADS + hh];
        v[i] = s; mx = fmaxf(mx, s);
    }
    __shared__ float red[256];
    red[t] = mx; __syncthreads();
    for (int o = 128; o; o >>= 1) { if (t < o) red[t] = fmaxf(red[t], red[t + o]); __syncthreads(); }
    mx = red[0]; __syncthreads();
    float sum = 0.f;
#pragma unroll
    for (int i = 0; i < E_DIM / 256; i++) { v[i] = __expf(v[i] - mx); sum += v[i]; }
    red[t] = sum; __syncthreads();
    for (int o = 128; o; o >>= 1) { if (t < o) red[t] += red[t + o]; __syncthreads(); }
    const float inv = 1.f / red[0];
#pragma unroll
    for (int i = 0; i < E_DIM / 256; i++)
        g_aeT[((long)bb * HEADS + hh) * E_DIM + i * 256 + t] = v[i] * inv;
}

// ---------------- launch ----------------
extern "C" void kernel_launch(void* const* d_in, const int* in_sizes, int n_in,
                              void* d_out, int out_size)
{
    const float* x = (const float*)d_in[0];
    const float* H = (const float*)d_in[1];
    const float* W = (const float*)d_in[2];
    const float* a = (const float*)d_in[3];
    float* out = (float*)d_out;

    __half *px16, *pW16T, *pHr16, *pHT16, *pWh16, *pWhT16, *pm2T16;
    float *paeT;
    cudaGetSymbolAddress((void**)&px16, g_x16);
    cudaGetSymbolAddress((void**)&pW16T, g_W16T);
    cudaGetSymbolAddress((void**)&pHr16, g_Hr16);
    cudaGetSymbolAddress((void**)&pHT16, g_HT16);
    cudaGetSymbolAddress((void**)&pWh16, g_Wh16);
    cudaGetSymbolAddress((void**)&pWhT16, g_WhT16);
    cudaGetSymbolAddress((void**)&pm2T16, g_m2T16);
    cudaGetSymbolAddress((void**)&paeT, g_aeT);

    cudaFuncSetAttribute(hgemm<0>, cudaFuncAttributeMaxDynamicSharedMemorySize, SMEM_SZ);
    cudaFuncSetAttribute(hgemm<1>, cudaFuncAttributeMaxDynamicSharedMemorySize, SMEM_SZ);
    cudaFuncSetAttribute(hgemm<2>, cudaFuncAttributeMaxDynamicSharedMemorySize, SMEM_SZ);

    // prep
    prep_pack<<<BATCH * N_DIM * FIN / 16 / 256, 256>>>(x, px16);
    prep_pack<<<(long)N_DIM * E_DIM / 16 / 256, 256>>>(H, pHr16);
    prep_WT<<<dim3(HD / 32, FIN / 32), 256>>>(W);
    prep_HT<<<dim3(E_DIM / 32, N_DIM / 32), 256>>>(H);

    // 1) Wh = x @ W (+ fused av) : M=16384, N=512, K=256
    hgemm<0><<<dim3(HD / 128, (BATCH * N_DIM) / 128, 1), 128, SMEM_SZ>>>(
        px16, pW16T, pWh16, FIN, FIN, FIN, HD, 0, 0, 0, a);
    // logits + softmax
    logits_kernel<<<dim3(E_DIM / 256, NSLICE), 256>>>(H);
    softmax_kernel<<<BATCH * HEADS, 256>>>();
    // transpose Wh
    trWh<<<dim3(HD / 32, BATCH * N_DIM / 32), 256>>>();
    // 5) m2T[b] = ae ⊙ (WhT[b] @ HT^T) : M=HD, N=E, K=N_DIM
    hgemm<1><<<dim3(E_DIM / 128, HD / 128, BATCH), 128, SMEM_SZ>>>(
        pWhT16, pHT16, pm2T16, N_DIM, N_DIM, N_DIM, E_DIM,
        (long)HD * N_DIM, 0, (long)HD * E_DIM, paeT);
    // 6) out[b] = Hr @ m2T[b]^T : M=N_DIM, N=HD, K=E
    hgemm<2><<<dim3(HD / 128, N_DIM / 128, BATCH), 128, SMEM_SZ>>>(
        pHr16, pm2T16, out, E_DIM, E_DIM, E_DIM, HD,
        0, (long)HD * E_DIM, (long)N_DIM * HD, nullptr);
}

// round 9
// speedup vs baseline: 1.8454x; 1.0003x over previous
#include <cuda_runtime.h>
#include <cuda_fp16.h>
#include <cstdint>

#define E_DIM 4096
#define N_DIM 8192
#define FIN   256
#define HEADS 8
#define DOUT  64
#define HD    512
#define BATCH 2
#define LRELU_ALPHA 0.2f
#define NSLICE 16

// ---------------- scratch (fp16 operands, k-perm16h columns) ----------------
__device__ __align__(16) __half g_x16[BATCH * N_DIM * FIN];
__device__ __align__(16) __half g_W16T[HD * FIN];
__device__ __align__(16) __half g_Hr16[N_DIM * E_DIM];     // (n, e-perm)
__device__ __align__(16) __half g_HT16[E_DIM * N_DIM];     // (e, n-perm)
__device__ __align__(16) __half g_Wh16[BATCH * N_DIM * HD];  // natural
__device__ __align__(16) __half g_WhT16[BATCH * HD * N_DIM]; // (hd, n-perm)
__device__ __align__(16) __half g_m2T16[BATCH * HD * E_DIM]; // (hd, e-perm), ae-scaled
__device__ float g_av[BATCH * N_DIM * HEADS];
__device__ float g_part[NSLICE * BATCH * E_DIM * HEADS];
__device__ float g_aeT[BATCH * HEADS * E_DIM];

__device__ __forceinline__ uint32_t smem_u32(const void* p) {
    uint32_t a;
    asm("{ .reg .u64 t; cvta.to.shared.u64 t, %1; cvt.u32.u64 %0, t; }" : "=r"(a) : "l"(p));
    return a;
}
__device__ __forceinline__ void lds64(uint32_t a, uint32_t& x, uint32_t& y) {
    asm volatile("ld.shared.v2.b32 {%0,%1}, [%2];" : "=r"(x), "=r"(y) : "r"(a));
}
__device__ __forceinline__ void cpa16(uint32_t dst, const void* src) {
    asm volatile("cp.async.cg.shared.global [%0], [%1], 16;" :: "r"(dst), "l"(src));
}
// within-16 k permutation: k -> ((k&6)<<1) | (((k>>3)&1)<<1) | (k&1)
// places the mma quad {2c,2c+1,2c+8,2c+9} at contiguous positions 4c..4c+3.
__device__ __host__ __forceinline__ int perm16h(int k) {
    return ((k & 6) << 1) | (((k >> 3) & 1) << 1) | (k & 1);
}

#define MMA_F16(c, a, b) \
    asm volatile("mma.sync.aligned.m16n8k16.row.col.f32.f16.f16.f32 " \
        "{%0,%1,%2,%3}, {%4,%5,%6,%7}, {%8,%9}, {%0,%1,%2,%3};" \
        : "+f"((c)[0]), "+f"((c)[1]), "+f"((c)[2]), "+f"((c)[3]) \
        : "r"((a)[0]), "r"((a)[1]), "r"((a)[2]), "r"((a)[3]), \
          "r"((b)[0]), "r"((b)[1]))

#define STG_BYTES 32768               // A 16KB + B 16KB (128 rows x 128B, 64 fp16/row)
#define STAGES 3
#define SMEM_SZ (STAGES * STG_BYTES)  // 96 KB

// ---------------- fp16 mma GEMM: CTA 128x128, 4 warps (64x64), K-step 64 ----------------
// A: (M x K) fp16, k-perm16h cols.  B: (N x K) fp16, k-perm16h cols.
// EPI 0: store fp16 natural + fused av (aeT = a_vertices)
// EPI 1: scale by aeT[bz,head(row),e(col)], fp16 store with perm16h cols
// EPI 2: fp32 plain store
template<int EPI>
__global__ void __launch_bounds__(128, 2) hgemm(
    const __half* __restrict__ A, const __half* __restrict__ B, void* __restrict__ Cv,
    int K, int lda, int ldb, int ldc,
    long strideA, long strideB, long strideC, const float* __restrict__ aeT)
{
    extern __shared__ char smem[];
    const uint32_t sb = smem_u32(smem);
    const int tid = threadIdx.x, lane = tid & 31, wid = tid >> 5;
    const int wm = wid >> 1, wn = wid & 1;
    const int m0 = blockIdx.y * 128, n0 = blockIdx.x * 128, bz = blockIdx.z;

    const __half* Ag = A + (long)bz * strideA + (long)m0 * lda;
    const __half* Bg = B + (long)bz * strideB + (long)n0 * ldb;

    auto load_stage = [&](int st, int k0) {
        const uint32_t sA = sb + st * STG_BYTES;
#pragma unroll
        for (int i = 0; i < 8; i++) {
            const int id = tid + i * 128;
            const int r = id >> 3, j = id & 7;
            cpa16(sA + r * 128 + ((j ^ ((r & 3) << 1)) << 4), Ag + (long)r * lda + k0 + j * 8);
        }
        const uint32_t sB = sA + 16384;
#pragma unroll
        for (int i = 0; i < 8; i++) {
            const int id = tid + i * 128;
            const int r = id >> 3, j = id & 7;
            cpa16(sB + r * 128 + ((j ^ ((r & 3) << 1)) << 4), Bg + (long)r * ldb + k0 + j * 8);
        }
    };

    float acc[4][8][4];
#pragma unroll
    for (int mt = 0; mt < 4; mt++)
#pragma unroll
        for (int nt = 0; nt < 8; nt++)
#pragma unroll
            for (int s = 0; s < 4; s++) acc[mt][nt][s] = 0.f;

    const int r4 = lane >> 2;
    const int cl = lane & 3;
    const int swz = (r4 & 3) << 1;
    const int c2 = cl >> 1;
    const int hof = (cl & 1) * 8;

    const int T = K / 64;
    load_stage(0, 0);
    asm volatile("cp.async.commit_group;" ::: "memory");
    load_stage(1, 64);
    asm volatile("cp.async.commit_group;" ::: "memory");

    for (int t = 0; t < T; t++) {
        asm volatile("cp.async.wait_group 1;" ::: "memory");
        __syncthreads();
        const int u = t + 2;
        if (u < T) load_stage(u % 3, u * 64);
        asm volatile("cp.async.commit_group;" ::: "memory");

        const uint32_t Ab = sb + (t % 3) * STG_BYTES;
        const uint32_t Bb = Ab + 16384;
        const uint32_t aBase = Ab + (wm * 64 + r4) * 128 + hof;
        const uint32_t bBase = Bb + (wn * 64 + r4) * 128 + hof;
#pragma unroll
        for (int kk = 0; kk < 4; kk++) {          // each kk = K=16
            const uint32_t gsb = (uint32_t)(((kk * 2 + c2) ^ swz) << 4);
            uint32_t af[4][4], bf[8][2];
#pragma unroll
            for (int mt = 0; mt < 4; mt++) {
                lds64(aBase + mt * 2048 + gsb, af[mt][0], af[mt][2]);
                lds64(aBase + mt * 2048 + 1024 + gsb, af[mt][1], af[mt][3]);
            }
#pragma unroll
            for (int nt = 0; nt < 8; nt++)
                lds64(bBase + nt * 1024 + gsb, bf[nt][0], bf[nt][1]);
#pragma unroll
            for (int mt = 0; mt < 4; mt++)
#pragma unroll
                for (int nt = 0; nt < 8; nt++)
                    MMA_F16(acc[mt][nt], af[mt], bf[nt]);
        }
    }

    // ---------------- epilogue ----------------
    if (EPI == 0) {
        __half* Cb = (__half*)Cv;                 // flat (B*N) x HD
        const int head = (n0 >> 6) + wn;
        float aw0[8], aw1[8];
#pragma unroll
        for (int nt = 0; nt < 8; nt++) {
            aw0[nt] = aeT[nt * 8 + 2 * cl];
            aw1[nt] = aeT[nt * 8 + 2 * cl + 1];
        }
#pragma unroll
        for (int mt = 0; mt < 4; mt++) {
            const int row = m0 + wm * 64 + mt * 16 + r4;
            float s0 = 0.f, s1 = 0.f;
#pragma unroll
            for (int nt = 0; nt < 8; nt++) {
                const int col = n0 + wn * 64 + nt * 8 + 2 * cl;
                const __half h0 = __float2half_rn(acc[mt][nt][0]);
                const __half h1 = __float2half_rn(acc[mt][nt][1]);
                const __half h2 = __float2half_rn(acc[mt][nt][2]);
                const __half h3 = __float2half_rn(acc[mt][nt][3]);
                *(__half2*)&Cb[(long)row * ldc + col] = __halves2half2(h0, h1);
                *(__half2*)&Cb[(long)(row + 8) * ldc + col] = __halves2half2(h2, h3);
                s0 += __half2float(h0) * aw0[nt] + __half2float(h1) * aw1[nt];
                s1 += __half2float(h2) * aw0[nt] + __half2float(h3) * aw1[nt];
            }
            s0 += __shfl_xor_sync(0xffffffffu, s0, 1);
            s0 += __shfl_xor_sync(0xffffffffu, s0, 2);
            s1 += __shfl_xor_sync(0xffffffffu, s1, 1);
            s1 += __shfl_xor_sync(0xffffffffu, s1, 2);
            if (cl == 0) {
                g_av[(long)row * HEADS + head] =
                    fmaxf(s0, 0.f) + LRELU_ALPHA * fminf(s0, 0.f);
                g_av[(long)(row + 8) * HEADS + head] =
                    fmaxf(s1, 0.f) + LRELU_ALPHA * fminf(s1, 0.f);
            }
        }
    } else if (EPI == 1) {
        __half* Cb = (__half*)Cv + (long)bz * strideC;
        const int head = (m0 >> 6) + wm;
        const float* aeb = aeT + ((long)bz * HEADS + head) * E_DIM;
        float sc0[8], sc1[8]; int cp[8];
#pragma unroll
        for (int nt = 0; nt < 8; nt++) {
            const int e = n0 + wn * 64 + nt * 8 + 2 * cl;   // even
            sc0[nt] = aeb[e]; sc1[nt] = aeb[e + 1];
            cp[nt] = (e & ~15) | perm16h(e & 15);           // cp+1 holds e+1
        }
#pragma unroll
        for (int mt = 0; mt < 4; mt++) {
            const int row = m0 + wm * 64 + mt * 16 + r4;
#pragma unroll
            for (int nt = 0; nt < 8; nt++) {
                *(__half2*)&Cb[(long)row * ldc + cp[nt]] = __halves2half2(
                    __float2half_rn(acc[mt][nt][0] * sc0[nt]),
                    __float2half_rn(acc[mt][nt][1] * sc1[nt]));
                *(__half2*)&Cb[(long)(row + 8) * ldc + cp[nt]] = __halves2half2(
                    __float2half_rn(acc[mt][nt][2] * sc0[nt]),
                    __float2half_rn(acc[mt][nt][3] * sc1[nt]));
            }
        }
    } else {
        float* Cb = (float*)Cv + (long)bz * strideC;
#pragma unroll
        for (int mt = 0; mt < 4; mt++) {
            const int row = m0 + wm * 64 + mt * 16 + r4;
#pragma unroll
            for (int nt = 0; nt < 8; nt++) {
                const int col = n0 + wn * 64 + nt * 8 + 2 * cl;
                float2 o0 = {acc[mt][nt][0], acc[mt][nt][1]};
                float2 o1 = {acc[mt][nt][2], acc[mt][nt][3]};
                *(float2*)&Cb[(long)row * ldc + col] = o0;
                *(float2*)&Cb[(long)(row + 8) * ldc + col] = o1;
            }
        }
    }
}

// ---------------- prep kernels ----------------
// generic: fp32 row-major -> fp16 with perm16h applied within each 16-col block
__global__ __launch_bounds__(256) void prep_pack(const float* __restrict__ src,
                                                 __half* __restrict__ dst) {
    const long idx = (long)blockIdx.x * 256 + threadIdx.x;   // 16-elem block id
    float f[16];
#pragma unroll
    for (int q = 0; q < 4; q++) {
        float4 v = ((const float4*)src)[idx * 4 + q];
        f[q * 4 + 0] = v.x; f[q * 4 + 1] = v.y; f[q * 4 + 2] = v.z; f[q * 4 + 3] = v.w;
    }
    __align__(16) __half hp[16];
#pragma unroll
    for (int k = 0; k < 16; k++) hp[perm16h(k)] = __float2half_rn(f[k]);
    ((uint4*)dst)[idx * 2] = ((const uint4*)hp)[0];
    ((uint4*)dst)[idx * 2 + 1] = ((const uint4*)hp)[1];
}
// W (FIN x HD) -> W16T (HD x FIN, k-perm16h)
__global__ __launch_bounds__(256) void prep_WT(const float* __restrict__ W) {
    __shared__ float ts[32][33];
    const int o0 = blockIdx.x * 32, i0 = blockIdx.y * 32;
    const int tx = threadIdx.x & 31, ty = threadIdx.x >> 5;
#pragma unroll
    for (int r8 = 0; r8 < 4; r8++) {
        const int il = ty + r8 * 8;
        ts[tx][il] = W[(long)(i0 + il) * HD + o0 + tx];
    }
    __syncthreads();
    const int txp = (tx & ~15) | perm16h(tx & 15);
#pragma unroll
    for (int r8 = 0; r8 < 4; r8++) {
        const int ol = ty + r8 * 8;
        g_W16T[(long)(o0 + ol) * FIN + i0 + txp] = __float2half_rn(ts[ol][tx]);
    }
}
// H (N x E) -> HT16 (E x N, n-perm16h)
__global__ __launch_bounds__(256) void prep_HT(const float* __restrict__ H) {
    __shared__ float ts[32][33];
    const int e0 = blockIdx.x * 32, n0 = blockIdx.y * 32;
    const int tx = threadIdx.x & 31, ty = threadIdx.x >> 5;
#pragma unroll
    for (int r8 = 0; r8 < 4; r8++) {
        const int nl = ty + r8 * 8;
        ts[tx][nl] = H[(long)(n0 + nl) * E_DIM + e0 + tx];   // ts[e_l][n_l]
    }
    __syncthreads();
    const int txp = (tx & ~15) | perm16h(tx & 15);
#pragma unroll
    for (int r8 = 0; r8 < 4; r8++) {
        const int el = ty + r8 * 8;
        g_HT16[(long)(e0 + el) * N_DIM + n0 + txp] = __float2half_rn(ts[el][tx]);
    }
}
// Wh16 (B*N x HD) -> WhT16 (B, HD, N n-perm16h)
__global__ __launch_bounds__(256) void trWh() {
    __shared__ __half ts[32][34];
    const int h0 = blockIdx.x * 32;
    const int n0g = blockIdx.y * 32;
    const int b = n0g >> 13, nn0 = n0g & (N_DIM - 1);
    const int tx = threadIdx.x & 31, ty = threadIdx.x >> 5;
#pragma unroll
    for (int r8 = 0; r8 < 4; r8++) {
        const int nl = ty + r8 * 8;
        ts[tx][nl] = g_Wh16[(long)(n0g + nl) * HD + h0 + tx];  // ts[hd_l][n_l]
    }
    __syncthreads();
    const int txp = (tx & ~15) | perm16h(tx & 15);
#pragma unroll
    for (int r8 = 0; r8 < 4; r8++) {
        const int hl = ty + r8 * 8;
        g_WhT16[((long)b * HD + h0 + hl) * N_DIM + nn0 + txp] = ts[hl][tx];
    }
}

// ---------------- logits / softmax (exact fp32) ----------------
__global__ __launch_bounds__(256) void logits_kernel(const float* __restrict__ H) {
    const int e = blockIdx.x * 256 + threadIdx.x;
    const int slice = blockIdx.y;
    const int nbeg = slice * (N_DIM / NSLICE);
    float acc[16];
#pragma unroll
    for (int j = 0; j < 16; j++) acc[j] = 0.f;
    __shared__ float avs[64][16];
    for (int nc = 0; nc < N_DIM / NSLICE; nc += 64) {
        __syncthreads();
        for (int i = threadIdx.x; i < 64 * 16; i += 256) {
            const int nn = i >> 4, bh = i & 15;
            avs[nn][bh] = g_av[((long)(bh >> 3) * N_DIM + nbeg + nc + nn) * HEADS + (bh & 7)];
        }
        __syncthreads();
        for (int nn = 0; nn < 64; nn++) {
            const float hv = H[(long)(nbeg + nc + nn) * E_DIM + e];
#pragma unroll
            for (int j = 0; j < 16; j++) acc[j] += hv * avs[nn][j];
        }
    }
#pragma unroll
    for (int j = 0; j < 16; j++)
        g_part[(((long)slice * BATCH + (j >> 3)) * E_DIM + e) * HEADS + (j & 7)] = acc[j];
}

__global__ __launch_bounds__(256) void softmax_kernel() {
    const int bb = blockIdx.x >> 3, hh = blockIdx.x & 7;
    const int t = threadIdx.x;
    float v[E_DIM / 256];
    float mx = -1e30f;
#pragma unroll
    for (int i = 0; i < E_DIM / 256; i++) {
        const int e = i * 256 + t;
        float s = 0.f;
        for (int sl = 0; sl < NSLICE; sl++)
            s += g_part[(((long)sl * BATCH + bb) * E_DIM + e) * HEADS + hh];
        v[i] = s; mx = fmaxf(mx, s);
    }
    __shared__ float red[256];
    red[t] = mx; __syncthreads();
    for (int o = 128; o; o >>= 1) { if (t < o) red[t] = fmaxf(red[t], red[t + o]); __syncthreads(); }
    mx = red[0]; __syncthreads();
    float sum = 0.f;
#pragma unroll
    for (int i = 0; i < E_DIM / 256; i++) { v[i] = __expf(v[i] - mx); sum += v[i]; }
    red[t] = sum; __syncthreads();
    for (int o = 128; o; o >>= 1) { if (t < o) red[t] += red[t + o]; __syncthreads(); }
    const float inv = 1.f / red[0];
#pragma unroll
    for (int i = 0; i < E_DIM / 256; i++)
        g_aeT[((long)bb * HEADS + hh) * E_DIM + i * 256 + t] = v[i] * inv;
}

// ---------------- launch ----------------
extern "C" void kernel_launch(void* const* d_in, const int* in_sizes, int n_in,
                              void* d_out, int out_size)
{
    const float* x = (const float*)d_in[0];
    const float* H = (const float*)d_in[1];
    const float* W = (const float*)d_in[2];
    const float* a = (const float*)d_in[3];
    float* out = (float*)d_out;

    __half *px16, *pW16T, *pHr16, *pHT16, *pWh16, *pWhT16, *pm2T16;
    float *paeT;
    cudaGetSymbolAddress((void**)&px16, g_x16);
    cudaGetSymbolAddress((void**)&pW16T, g_W16T);
    cudaGetSymbolAddress((void**)&pHr16, g_Hr16);
    cudaGetSymbolAddress((void**)&pHT16, g_HT16);
    cudaGetSymbolAddress((void**)&pWh16, g_Wh16);
    cudaGetSymbolAddress((void**)&pWhT16, g_WhT16);
    cudaGetSymbolAddress((void**)&pm2T16, g_m2T16);
    cudaGetSymbolAddress((void**)&paeT, g_aeT);

    cudaFuncSetAttribute(hgemm<0>, cudaFuncAttributeMaxDynamicSharedMemorySize, SMEM_SZ);
    cudaFuncSetAttribute(hgemm<1>, cudaFuncAttributeMaxDynamicSharedMemorySize, SMEM_SZ);
    cudaFuncSetAttribute(hgemm<2>, cudaFuncAttributeMaxDynamicSharedMemorySize, SMEM_SZ);

    // prep
    prep_pack<<<BATCH * N_DIM * FIN / 16 / 256, 256>>>(x, px16);
    prep_pack<<<(long)N_DIM * E_DIM / 16 / 256, 256>>>(H, pHr16);
    prep_WT<<<dim3(HD / 32, FIN / 32), 256>>>(W);
    prep_HT<<<dim3(E_DIM / 32, N_DIM / 32), 256>>>(H);

    // 1) Wh = x @ W (+ fused av) : M=16384, N=512, K=256
    hgemm<0><<<dim3(HD / 128, (BATCH * N_DIM) / 128, 1), 128, SMEM_SZ>>>(
        px16, pW16T, pWh16, FIN, FIN, FIN, HD, 0, 0, 0, a);
    // logits + softmax
    logits_kernel<<<dim3(E_DIM / 256, NSLICE), 256>>>(H);
    softmax_kernel<<<BATCH * HEADS, 256>>>();
    // transpose Wh
    trWh<<<dim3(HD / 32, BATCH * N_DIM / 32), 256>>>();
    // 5) m2T[b] = ae ⊙ (WhT[b] @ HT^T) : M=HD, N=E, K=N_DIM
    hgemm<1><<<dim3(E_DIM / 128, HD / 128, BATCH), 128, SMEM_SZ>>>(
        pWhT16, pHT16, pm2T16, N_DIM, N_DIM, N_DIM, E_DIM,
        (long)HD * N_DIM, 0, (long)HD * E_DIM, paeT);
    // 6) out[b] = Hr @ m2T[b]^T : M=N_DIM, N=HD, K=E
    hgemm<2><<<dim3(HD / 128, N_DIM / 128, BATCH), 128, SMEM_SZ>>>(
        pHr16, pm2T16, out, E_DIM, E_DIM, E_DIM, HD,
        0, (long)HD * E_DIM, (long)N_DIM * HD, nullptr);
}

// round 10
// speedup vs baseline: 2.0069x; 1.0875x over previous
#include <cuda_runtime.h>
#include <cuda_fp16.h>
#include <cstdint>

#define E_DIM 4096
#define N_DIM 8192
#define FIN   256
#define HEADS 8
#define DOUT  64
#define HD    512
#define BATCH 2
#define LRELU_ALPHA 0.2f
#define NSLICE 16

// ---------------- scratch (fp16 operands, natural K-major layout) ----------------
__device__ __align__(16) __half g_x16[BATCH * N_DIM * FIN];
__device__ __align__(16) __half g_W16T[HD * FIN];
__device__ __align__(16) __half g_Hr16[N_DIM * E_DIM];       // (n, e)
__device__ __align__(16) __half g_HT16[E_DIM * N_DIM];       // (e, n)
__device__ __align__(16) __half g_Wh16[BATCH * N_DIM * HD];  // natural
__device__ __align__(16) __half g_WhT16[BATCH * HD * N_DIM]; // (hd, n)
__device__ __align__(16) __half g_m2T16[BATCH * HD * E_DIM]; // (hd, e), ae-scaled
__device__ float g_av[BATCH * N_DIM * HEADS];
__device__ float g_part[NSLICE * BATCH * E_DIM * HEADS];
__device__ float g_aeT[BATCH * HEADS * E_DIM];

__device__ __forceinline__ uint32_t smem_u32(const void* p) {
    uint32_t a;
    asm("{ .reg .u64 t; cvta.to.shared.u64 t, %1; cvt.u32.u64 %0, t; }" : "=r"(a) : "l"(p));
    return a;
}
__device__ __forceinline__ void cpa16(uint32_t dst, const void* src) {
    asm volatile("cp.async.cg.shared.global [%0], [%1], 16;" :: "r"(dst), "l"(src));
}
#define LDSM4(r0, r1, r2, r3, addr) \
    asm volatile("ldmatrix.sync.aligned.m8n8.x4.shared.b16 {%0,%1,%2,%3}, [%4];" \
        : "=r"(r0), "=r"(r1), "=r"(r2), "=r"(r3) : "r"(addr))

#define MMA_F16(c, a, b) \
    asm volatile("mma.sync.aligned.m16n8k16.row.col.f32.f16.f16.f32 " \
        "{%0,%1,%2,%3}, {%4,%5,%6,%7}, {%8,%9}, {%0,%1,%2,%3};" \
        : "+f"((c)[0]), "+f"((c)[1]), "+f"((c)[2]), "+f"((c)[3]) \
        : "r"((a)[0]), "r"((a)[1]), "r"((a)[2]), "r"((a)[3]), \
          "r"((b)[0]), "r"((b)[1]))

#define STG_BYTES 32768               // A 16KB + B 16KB (128 rows x 128B = 64 fp16)
#define STAGES 3
#define SMEM_SZ (STAGES * STG_BYTES)  // 96 KB

// ---------------- fp16 mma GEMM: CTA 128x128, 4 warps (64x64), K-step 64 ----------------
// A: (M x K) fp16 K-major.  B: (N x K) fp16 K-major.  smem swizzle: group j ^ (row & 7).
// EPI 0: fp16 natural store + fused av (aeT = a_vertices)
// EPI 1: scale by aeT[bz,head(row),e(col)], fp16 natural store
// EPI 2: fp32 plain store
template<int EPI>
__global__ void __launch_bounds__(128, 2) hgemm(
    const __half* __restrict__ A, const __half* __restrict__ B, void* __restrict__ Cv,
    int K, int lda, int ldb, int ldc,
    long strideA, long strideB, long strideC, const float* __restrict__ aeT)
{
    extern __shared__ char smem[];
    const uint32_t sb = smem_u32(smem);
    const int tid = threadIdx.x, lane = tid & 31, wid = tid >> 5;
    const int wm = wid >> 1, wn = wid & 1;
    const int m0 = blockIdx.y * 128, n0 = blockIdx.x * 128, bz = blockIdx.z;

    const __half* Ag = A + (long)bz * strideA + (long)m0 * lda;
    const __half* Bg = B + (long)bz * strideB + (long)n0 * ldb;

    auto load_stage = [&](int st, int k0) {
        const uint32_t sA = sb + st * STG_BYTES;
#pragma unroll
        for (int i = 0; i < 8; i++) {
            const int id = tid + i * 128;
            const int r = id >> 3, j = id & 7;
            cpa16(sA + r * 128 + ((j ^ (r & 7)) << 4), Ag + (long)r * lda + k0 + j * 8);
        }
        const uint32_t sB = sA + 16384;
#pragma unroll
        for (int i = 0; i < 8; i++) {
            const int id = tid + i * 128;
            const int r = id >> 3, j = id & 7;
            cpa16(sB + r * 128 + ((j ^ (r & 7)) << 4), Bg + (long)r * ldb + k0 + j * 8);
        }
    };

    float acc[4][8][4];
#pragma unroll
    for (int mt = 0; mt < 4; mt++)
#pragma unroll
        for (int nt = 0; nt < 8; nt++)
#pragma unroll
            for (int s = 0; s < 4; s++) acc[mt][nt][s] = 0.f;

    // ldmatrix per-lane geometry
    const int l7 = lane & 7, sub = lane >> 3;
    const int rowAl = (sub & 1) * 8 + l7;   // A: matrices M00,M10,M01,M11
    const int kgA = sub >> 1;
    const int rowBl = (sub >> 1) * 8 + l7;  // B: matrices b0(nt),b1(nt),b0(nt+1),b1(nt+1)
    const int kgB = sub & 1;

    const int T = K / 64;
    load_stage(0, 0);
    asm volatile("cp.async.commit_group;" ::: "memory");
    load_stage(1, 64);
    asm volatile("cp.async.commit_group;" ::: "memory");

    for (int t = 0; t < T; t++) {
        asm volatile("cp.async.wait_group 1;" ::: "memory");
        __syncthreads();
        const int u = t + 2;
        if (u < T) load_stage(u % 3, u * 64);
        asm volatile("cp.async.commit_group;" ::: "memory");

        const uint32_t Ab = sb + (t % 3) * STG_BYTES;
        const uint32_t Bb = Ab + 16384;
        const uint32_t aRow = Ab + (wm * 64 + rowAl) * 128;
        const uint32_t bRow = Bb + (wn * 64 + rowBl) * 128;
#pragma unroll
        for (int kk = 0; kk < 4; kk++) {          // each kk = K=16
            const uint32_t gA = (uint32_t)((((kk << 1) | kgA) ^ l7) << 4);
            const uint32_t gB = (uint32_t)((((kk << 1) | kgB) ^ l7) << 4);
            uint32_t af[4][4], bf[8][2];
#pragma unroll
            for (int mt = 0; mt < 4; mt++)
                LDSM4(af[mt][0], af[mt][1], af[mt][2], af[mt][3],
                      aRow + mt * 16 * 128 + gA);
#pragma unroll
            for (int np = 0; np < 4; np++)
                LDSM4(bf[2 * np][0], bf[2 * np][1], bf[2 * np + 1][0], bf[2 * np + 1][1],
                      bRow + np * 16 * 128 + gB);
#pragma unroll
            for (int mt = 0; mt < 4; mt++)
#pragma unroll
                for (int nt = 0; nt < 8; nt++)
                    MMA_F16(acc[mt][nt], af[mt], bf[nt]);
        }
    }

    // ---------------- epilogue ----------------
    const int r4 = lane >> 2, cl = lane & 3;
    if (EPI == 0) {
        __half* Cb = (__half*)Cv;                 // flat (B*N) x HD
        const int head = (n0 >> 6) + wn;
        float aw0[8], aw1[8];
#pragma unroll
        for (int nt = 0; nt < 8; nt++) {
            aw0[nt] = aeT[nt * 8 + 2 * cl];
            aw1[nt] = aeT[nt * 8 + 2 * cl + 1];
        }
#pragma unroll
        for (int mt = 0; mt < 4; mt++) {
            const int row = m0 + wm * 64 + mt * 16 + r4;
            float s0 = 0.f, s1 = 0.f;
#pragma unroll
            for (int nt = 0; nt < 8; nt++) {
                const int col = n0 + wn * 64 + nt * 8 + 2 * cl;
                const __half h0 = __float2half_rn(acc[mt][nt][0]);
                const __half h1 = __float2half_rn(acc[mt][nt][1]);
                const __half h2 = __float2half_rn(acc[mt][nt][2]);
                const __half h3 = __float2half_rn(acc[mt][nt][3]);
                *(__half2*)&Cb[(long)row * ldc + col] = __halves2half2(h0, h1);
                *(__half2*)&Cb[(long)(row + 8) * ldc + col] = __halves2half2(h2, h3);
                s0 += __half2float(h0) * aw0[nt] + __half2float(h1) * aw1[nt];
                s1 += __half2float(h2) * aw0[nt] + __half2float(h3) * aw1[nt];
            }
            s0 += __shfl_xor_sync(0xffffffffu, s0, 1);
            s0 += __shfl_xor_sync(0xffffffffu, s0, 2);
            s1 += __shfl_xor_sync(0xffffffffu, s1, 1);
            s1 += __shfl_xor_sync(0xffffffffu, s1, 2);
            if (cl == 0) {
                g_av[(long)row * HEADS + head] =
                    fmaxf(s0, 0.f) + LRELU_ALPHA * fminf(s0, 0.f);
                g_av[(long)(row + 8) * HEADS + head] =
                    fmaxf(s1, 0.f) + LRELU_ALPHA * fminf(s1, 0.f);
            }
        }
    } else if (EPI == 1) {
        __half* Cb = (__half*)Cv + (long)bz * strideC;
        const int head = (m0 >> 6) + wm;
        const float* aeb = aeT + ((long)bz * HEADS + head) * E_DIM;
        float sc0[8], sc1[8];
#pragma unroll
        for (int nt = 0; nt < 8; nt++) {
            const int e = n0 + wn * 64 + nt * 8 + 2 * cl;
            sc0[nt] = aeb[e]; sc1[nt] = aeb[e + 1];
        }
#pragma unroll
        for (int mt = 0; mt < 4; mt++) {
            const int row = m0 + wm * 64 + mt * 16 + r4;
#pragma unroll
            for (int nt = 0; nt < 8; nt++) {
                const int col = n0 + wn * 64 + nt * 8 + 2 * cl;
                *(__half2*)&Cb[(long)row * ldc + col] = __halves2half2(
                    __float2half_rn(acc[mt][nt][0] * sc0[nt]),
                    __float2half_rn(acc[mt][nt][1] * sc1[nt]));
                *(__half2*)&Cb[(long)(row + 8) * ldc + col] = __halves2half2(
                    __float2half_rn(acc[mt][nt][2] * sc0[nt]),
                    __float2half_rn(acc[mt][nt][3] * sc1[nt]));
            }
        }
    } else {
        float* Cb = (float*)Cv + (long)bz * strideC;
#pragma unroll
        for (int mt = 0; mt < 4; mt++) {
            const int row = m0 + wm * 64 + mt * 16 + r4;
#pragma unroll
            for (int nt = 0; nt < 8; nt++) {
                const int col = n0 + wn * 64 + nt * 8 + 2 * cl;
                float2 o0 = {acc[mt][nt][0], acc[mt][nt][1]};
                float2 o1 = {acc[mt][nt][2], acc[mt][nt][3]};
                *(float2*)&Cb[(long)row * ldc + col] = o0;
                *(float2*)&Cb[(long)(row + 8) * ldc + col] = o1;
            }
        }
    }
}

// ---------------- prep kernels (natural layout, no permutation) ----------------
__global__ __launch_bounds__(256) void prep_pack(const float* __restrict__ src,
                                                 __half* __restrict__ dst) {
    const long i = (long)blockIdx.x * 256 + threadIdx.x;   // 8-elem block
    float4 v0 = ((const float4*)src)[i * 2];
    float4 v1 = ((const float4*)src)[i * 2 + 1];
    __align__(16) __half h[8];
    h[0] = __float2half_rn(v0.x); h[1] = __float2half_rn(v0.y);
    h[2] = __float2half_rn(v0.z); h[3] = __float2half_rn(v0.w);
    h[4] = __float2half_rn(v1.x); h[5] = __float2half_rn(v1.y);
    h[6] = __float2half_rn(v1.z); h[7] = __float2half_rn(v1.w);
    ((uint4*)dst)[i] = *(const uint4*)h;
}
// W (FIN x HD) -> W16T (HD x FIN)
__global__ __launch_bounds__(256) void prep_WT(const float* __restrict__ W) {
    __shared__ float ts[32][33];
    const int o0 = blockIdx.x * 32, i0 = blockIdx.y * 32;
    const int tx = threadIdx.x & 31, ty = threadIdx.x >> 5;
#pragma unroll
    for (int r8 = 0; r8 < 4; r8++) {
        const int il = ty + r8 * 8;
        ts[tx][il] = W[(long)(i0 + il) * HD + o0 + tx];
    }
    __syncthreads();
#pragma unroll
    for (int r8 = 0; r8 < 4; r8++) {
        const int ol = ty + r8 * 8;
        g_W16T[(long)(o0 + ol) * FIN + i0 + tx] = __float2half_rn(ts[ol][tx]);
    }
}
// H (N x E) -> Hr16 (N x E) AND HT16 (E x N), single pass over H
__global__ __launch_bounds__(256) void prep_H(const float* __restrict__ H) {
    __shared__ __half ts[32][34];
    const int e0 = blockIdx.x * 32, n0 = blockIdx.y * 32;
    const int tx = threadIdx.x & 31, ty = threadIdx.x >> 5;
#pragma unroll
    for (int r8 = 0; r8 < 4; r8++) {
        const int nl = ty + r8 * 8;
        const __half h = __float2half_rn(H[(long)(n0 + nl) * E_DIM + e0 + tx]);
        g_Hr16[(long)(n0 + nl) * E_DIM + e0 + tx] = h;
        ts[tx][nl] = h;                                   // ts[e_l][n_l]
    }
    __syncthreads();
#pragma unroll
    for (int r8 = 0; r8 < 4; r8++) {
        const int el = ty + r8 * 8;
        g_HT16[(long)(e0 + el) * N_DIM + n0 + tx] = ts[el][tx];
    }
}
// Wh16 (B*N x HD) -> WhT16 (B, HD, N)
__global__ __launch_bounds__(256) void trWh() {
    __shared__ __half ts[32][34];
    const int h0 = blockIdx.x * 32;
    const int n0g = blockIdx.y * 32;
    const int b = n0g >> 13, nn0 = n0g & (N_DIM - 1);
    const int tx = threadIdx.x & 31, ty = threadIdx.x >> 5;
#pragma unroll
    for (int r8 = 0; r8 < 4; r8++) {
        const int nl = ty + r8 * 8;
        ts[tx][nl] = g_Wh16[(long)(n0g + nl) * HD + h0 + tx];  // ts[hd_l][n_l]
    }
    __syncthreads();
#pragma unroll
    for (int r8 = 0; r8 < 4; r8++) {
        const int hl = ty + r8 * 8;
        g_WhT16[((long)b * HD + h0 + hl) * N_DIM + nn0 + tx] = ts[hl][tx];
    }
}

// ---------------- logits / softmax (exact fp32) ----------------
__global__ __launch_bounds__(256) void logits_kernel(const float* __restrict__ H) {
    const int e = blockIdx.x * 256 + threadIdx.x;
    const int slice = blockIdx.y;
    const int nbeg = slice * (N_DIM / NSLICE);
    float acc[16];
#pragma unroll
    for (int j = 0; j < 16; j++) acc[j] = 0.f;
    __shared__ float avs[64][16];
    for (int nc = 0; nc < N_DIM / NSLICE; nc += 64) {
        __syncthreads();
        for (int i = threadIdx.x; i < 64 * 16; i += 256) {
            const int nn = i >> 4, bh = i & 15;
            avs[nn][bh] = g_av[((long)(bh >> 3) * N_DIM + nbeg + nc + nn) * HEADS + (bh & 7)];
        }
        __syncthreads();
        for (int nn = 0; nn < 64; nn++) {
            const float hv = H[(long)(nbeg + nc + nn) * E_DIM + e];
#pragma unroll
            for (int j = 0; j < 16; j++) acc[j] += hv * avs[nn][j];
        }
    }
#pragma unroll
    for (int j = 0; j < 16; j++)
        g_part[(((long)slice * BATCH + (j >> 3)) * E_DIM + e) * HEADS + (j & 7)] = acc[j];
}

__global__ __launch_bounds__(1024) void softmax_kernel() {
    const int bb = blockIdx.x >> 3, hh = blockIdx.x & 7;
    const int t = threadIdx.x;
    float v[E_DIM / 1024];
    float mx = -1e30f;
#pragma unroll
    for (int i = 0; i < E_DIM / 1024; i++) {
        const int e = i * 1024 + t;
        float s = 0.f;
        for (int sl = 0; sl < NSLICE; sl++)
            s += g_part[(((long)sl * BATCH + bb) * E_DIM + e) * HEADS + hh];
        v[i] = s; mx = fmaxf(mx, s);
    }
    __shared__ float red[1024];
    red[t] = mx; __syncthreads();
    for (int o = 512; o; o >>= 1) { if (t < o) red[t] = fmaxf(red[t], red[t + o]); __syncthreads(); }
    mx = red[0]; __syncthreads();
    float sum = 0.f;
#pragma unroll
    for (int i = 0; i < E_DIM / 1024; i++) { v[i] = __expf(v[i] - mx); sum += v[i]; }
    red[t] = sum; __syncthreads();
    for (int o = 512; o; o >>= 1) { if (t < o) red[t] += red[t + o]; __syncthreads(); }
    const float inv = 1.f / red[0];
#pragma unroll
    for (int i = 0; i < E_DIM / 1024; i++)
        g_aeT[((long)bb * HEADS + hh) * E_DIM + i * 1024 + t] = v[i] * inv;
}

// ---------------- launch ----------------
extern "C" void kernel_launch(void* const* d_in, const int* in_sizes, int n_in,
                              void* d_out, int out_size)
{
    const float* x = (const float*)d_in[0];
    const float* H = (const float*)d_in[1];
    const float* W = (const float*)d_in[2];
    const float* a = (const float*)d_in[3];
    float* out = (float*)d_out;

    __half *px16, *pW16T, *pHr16, *pHT16, *pWh16, *pWhT16, *pm2T16;
    float *paeT;
    cudaGetSymbolAddress((void**)&px16, g_x16);
    cudaGetSymbolAddress((void**)&pW16T, g_W16T);
    cudaGetSymbolAddress((void**)&pHr16, g_Hr16);
    cudaGetSymbolAddress((void**)&pHT16, g_HT16);
    cudaGetSymbolAddress((void**)&pWh16, g_Wh16);
    cudaGetSymbolAddress((void**)&pWhT16, g_WhT16);
    cudaGetSymbolAddress((void**)&pm2T16, g_m2T16);
    cudaGetSymbolAddress((void**)&paeT, g_aeT);

    cudaFuncSetAttribute(hgemm<0>, cudaFuncAttributeMaxDynamicSharedMemorySize, SMEM_SZ);
    cudaFuncSetAttribute(hgemm<1>, cudaFuncAttributeMaxDynamicSharedMemorySize, SMEM_SZ);
    cudaFuncSetAttribute(hgemm<2>, cudaFuncAttributeMaxDynamicSharedMemorySize, SMEM_SZ);

    // prep
    prep_pack<<<BATCH * N_DIM * FIN / 8 / 256, 256>>>(x, px16);
    prep_WT<<<dim3(HD / 32, FIN / 32), 256>>>(W);
    prep_H<<<dim3(E_DIM / 32, N_DIM / 32), 256>>>(H);   // Hr16 + HT16 in one pass

    // 1) Wh = x @ W (+ fused av) : M=16384, N=512, K=256
    hgemm<0><<<dim3(HD / 128, (BATCH * N_DIM) / 128, 1), 128, SMEM_SZ>>>(
        px16, pW16T, pWh16, FIN, FIN, FIN, HD, 0, 0, 0, a);
    // logits + softmax
    logits_kernel<<<dim3(E_DIM / 256, NSLICE), 256>>>(H);
    softmax_kernel<<<BATCH * HEADS, 1024>>>();
    // transpose Wh
    trWh<<<dim3(HD / 32, BATCH * N_DIM / 32), 256>>>();
    // 5) m2T[b] = ae ⊙ (WhT[b] @ HT^T) : M=HD, N=E, K=N_DIM
    hgemm<1><<<dim3(E_DIM / 128, HD / 128, BATCH), 128, SMEM_SZ>>>(
        pWhT16, pHT16, pm2T16, N_DIM, N_DIM, N_DIM, E_DIM,
        (long)HD * N_DIM, 0, (long)HD * E_DIM, paeT);
    // 6) out[b] = Hr @ m2T[b]^T : M=N_DIM, N=HD, K=E
    hgemm<2><<<dim3(HD / 128, N_DIM / 128, BATCH), 128, SMEM_SZ>>>(
        pHr16, pm2T16, out, E_DIM, E_DIM, E_DIM, HD,
        0, (long)HD * E_DIM, (long)N_DIM * HD, nullptr);
}